// round 1
// baseline (speedup 1.0000x reference)
#include <cuda_runtime.h>
#include <cuda_bf16.h>
#include <math.h>

// ---------------- problem constants ----------------
constexpr int B_   = 2;
constexpr int T_   = 2048;
constexpr int D_   = 2048;
constexpr int H_   = 16;
constexpr int NOPE = 128;
constexpr int ROPE = 64;
constexpr int QH   = NOPE + ROPE;          // 192
constexpr int QL   = H_ * QH / 4;          // 768
constexpr int KVR  = 512;
constexpr int VD   = 128;
constexpr int MT   = B_ * T_;              // 4096 rows
constexpr int KVN  = H_ * (NOPE + VD);     // 4096
constexpr int QN   = H_ * QH;              // 3072
constexpr float EPS = 1e-6f;
constexpr float SCALE = 0.07216878364870322f; // 192^-0.5

// ---------------- scratch (static device memory; no runtime alloc) ----------------
__device__ float g_qlora[(size_t)MT * QL];        // x@w_qa, then rms'd in place
__device__ float g_q[(size_t)MT * QN];            // q after w_qb, rope applied in place
__device__ float g_kvc[(size_t)MT * (KVR + ROPE)];// x@w_kva
__device__ float g_ckv[(size_t)MT * KVR];         // normalized c_kv
__device__ float g_kv[(size_t)MT * KVN];          // ckv@w_kvb
__device__ float g_krope[(size_t)MT * ROPE];      // roped k (attention operand)
__device__ float g_attn[(size_t)MT * (H_ * VD)];  // attention output (pre w_o)

// ---------------- generic SGEMM: C = A(M,K) @ B(K,N), row-major ----------------
// 128x128 tile, BK=8, 256 threads, 8x8 micro-tile. M%128==0, K%8==0 assumed; N guarded.
__global__ __launch_bounds__(256) void sgemm_kernel(
    const float* __restrict__ A, const float* __restrict__ Bm,
    float* __restrict__ C, int M, int N, int K)
{
    __shared__ float As[8][128];
    __shared__ float Bs[8][128];

    const int tid = threadIdx.x;
    const int m0 = blockIdx.y * 128;
    const int n0 = blockIdx.x * 128;
    const int tx = tid & 15;
    const int ty = tid >> 4;

    const int arow = tid >> 1;
    const int acol = (tid & 1) * 4;
    const int brow = tid >> 5;
    const int bcol = (tid & 31) * 4;

    float acc[8][8];
#pragma unroll
    for (int i = 0; i < 8; i++)
#pragma unroll
        for (int j = 0; j < 8; j++) acc[i][j] = 0.f;

    const int kTiles = K >> 3;
    for (int kt = 0; kt < kTiles; kt++) {
        const int k0 = kt * 8;
        // A tile (128x8), transposed into As[k][m]
        float4 av = *(const float4*)(A + (size_t)(m0 + arow) * K + k0 + acol);
        As[acol + 0][arow] = av.x;
        As[acol + 1][arow] = av.y;
        As[acol + 2][arow] = av.z;
        As[acol + 3][arow] = av.w;
        // B tile (8x128), N-guarded
        const int bc = n0 + bcol;
        const float* bp = Bm + (size_t)(k0 + brow) * N + bc;
        float4 bv;
        if (bc + 3 < N) {
            bv = *(const float4*)bp;
        } else {
            bv.x = (bc + 0 < N) ? bp[0] : 0.f;
            bv.y = (bc + 1 < N) ? bp[1] : 0.f;
            bv.z = (bc + 2 < N) ? bp[2] : 0.f;
            bv.w = (bc + 3 < N) ? bp[3] : 0.f;
        }
        *(float4*)&Bs[brow][bcol] = bv;
        __syncthreads();
#pragma unroll
        for (int k = 0; k < 8; k++) {
            float4 a0 = *(const float4*)&As[k][ty * 8];
            float4 a1 = *(const float4*)&As[k][ty * 8 + 4];
            float4 b0 = *(const float4*)&Bs[k][tx * 8];
            float4 b1 = *(const float4*)&Bs[k][tx * 8 + 4];
            float ar[8] = {a0.x, a0.y, a0.z, a0.w, a1.x, a1.y, a1.z, a1.w};
            float br[8] = {b0.x, b0.y, b0.z, b0.w, b1.x, b1.y, b1.z, b1.w};
#pragma unroll
            for (int i = 0; i < 8; i++)
#pragma unroll
                for (int j = 0; j < 8; j++)
                    acc[i][j] = fmaf(ar[i], br[j], acc[i][j]);
        }
        __syncthreads();
    }
#pragma unroll
    for (int i = 0; i < 8; i++) {
        const int row = m0 + ty * 8 + i;
        float* cp = C + (size_t)row * N + n0 + tx * 8;
#pragma unroll
        for (int j = 0; j < 8; j++) {
            const int col = n0 + tx * 8 + j;
            if (col < N) cp[j] = acc[i][j];
        }
    }
}

// ---------------- block reduce (sum) ----------------
__device__ __forceinline__ float block_sum(float v) {
    __shared__ float red[8];
    __shared__ float tot;
    const int lane = threadIdx.x & 31, w = threadIdx.x >> 5;
#pragma unroll
    for (int o = 16; o; o >>= 1) v += __shfl_xor_sync(0xffffffffu, v, o);
    if (lane == 0) red[w] = v;
    __syncthreads();
    if (w == 0) {
        float x = (threadIdx.x < (blockDim.x >> 5)) ? red[threadIdx.x] : 0.f;
#pragma unroll
        for (int o = 4; o; o >>= 1) x += __shfl_xor_sync(0xffffffffu, x, o);
        if (threadIdx.x == 0) tot = x;
    }
    __syncthreads();
    return tot;
}

// ---------------- RMSNorm (in place), ncols arbitrary ----------------
__global__ __launch_bounds__(256) void rms_kernel(
    float* __restrict__ X, const float* __restrict__ g, int ncols)
{
    const int row = blockIdx.x;
    float* x = X + (size_t)row * ncols;
    float ss = 0.f;
    for (int c = threadIdx.x; c < ncols; c += blockDim.x) { float v = x[c]; ss += v * v; }
    const float total = block_sum(ss);
    const float rs = rsqrtf(total / (float)ncols + EPS);
    for (int c = threadIdx.x; c < ncols; c += blockDim.x)
        x[c] = x[c] * rs * g[c];
}

// ---------------- kv path: rms(c_kv) -> outputs; split + rope k ----------------
__global__ __launch_bounds__(256) void rmskv_rope_kernel(
    const float* __restrict__ kvc, const float* __restrict__ g_kva_,
    float* __restrict__ ckv_scr, float* __restrict__ out_ckv,
    float* __restrict__ out_kr, float* __restrict__ kr_rot)
{
    const int row = blockIdx.x;       // b*T + t
    const int t = row % T_;
    const float* x = kvc + (size_t)row * (KVR + ROPE);
    float ss = 0.f;
    for (int c = threadIdx.x; c < KVR; c += blockDim.x) { float v = x[c]; ss += v * v; }
    const float total = block_sum(ss);
    const float rs = rsqrtf(total / (float)KVR + EPS);
    for (int c = threadIdx.x; c < KVR; c += blockDim.x) {
        const float v = x[c] * rs * g_kva_[c];
        ckv_scr[(size_t)row * KVR + c] = v;
        out_ckv[(size_t)row * KVR + c] = v;
    }
    if (threadIdx.x < ROPE) {
        const int d = threadIdx.x;
        const float raw = x[KVR + d];
        out_kr[(size_t)row * ROPE + d] = raw;
        const int j = d & 31;
        const float inv = powf(10000.f, -(float)(2 * j) / (float)ROPE);
        const float fr = (float)t * inv;
        const float other = (d < 32) ? -x[KVR + d + 32] : x[KVR + d - 32];
        kr_rot[(size_t)row * ROPE + d] = raw * cosf(fr) + other * sinf(fr);
    }
}

// ---------------- rope for q (in place in g_q) ----------------
__global__ __launch_bounds__(1024) void rope_q_kernel(
    float* __restrict__ q, const int* __restrict__ positions)
{
    const int row = blockIdx.x;
    const int pos = positions[row];
    const int h = threadIdx.x >> 6;
    const int d = threadIdx.x & 63;
    float* qr = q + (size_t)row * QN + h * QH + NOPE;
    const float xv = qr[d];
    const float other = (d < 32) ? -qr[d + 32] : qr[d - 32];
    __syncthreads();
    const int j = d & 31;
    const float inv = powf(10000.f, -(float)(2 * j) / (float)ROPE);
    const float fr = (float)pos * inv;
    qr[d] = xv * cosf(fr) + other * sinf(fr);
}

// ---------------- flash attention ----------------
// grid (T/64, H, B), 256 threads. BM=BN=64.
constexpr int QS = 196;   // 192 padded, %32==4, 16B aligned
constexpr int VS = 132;   // 128 padded
constexpr int PS = 68;    // 64 padded
constexpr int ATTN_SMEM = (64 * QS * 2 + 64 * VS + 64 * PS) * 4; // 151552 bytes

__global__ __launch_bounds__(256) void attn_kernel(
    const float* __restrict__ Q, const float* __restrict__ KV,
    const float* __restrict__ KR, float* __restrict__ O)
{
    extern __shared__ float sm[];
    float* sQ = sm;
    float* sK = sQ + 64 * QS;
    float* sV = sK + 64 * QS;
    float* sP = sV + 64 * VS;

    const int qt = blockIdx.x;
    const int h  = blockIdx.y;
    const int b  = blockIdx.z;
    const int q0 = qt * 64;
    const size_t bT = (size_t)b * T_;
    const int tid = threadIdx.x;

    // load Q tile 64x192 (nope + roped rope, already contiguous in g_q)
    for (int idx = tid; idx < 64 * 192; idx += 256) {
        const int i = idx / 192, d = idx % 192;
        sQ[i * QS + d] = Q[(bT + q0 + i) * QN + h * QH + d];
    }

    const int r = tid >> 2;
    const int jg = (tid & 3) * 16;
    const int cbase = (tid & 3) * 32;

    float m = -1e30f, l = 0.f;
    float acc[32];
#pragma unroll
    for (int c = 0; c < 32; c++) acc[c] = 0.f;

    __syncthreads();

    const int nchunks = qt + 1;   // causal: skip fully masked chunks
    for (int ch = 0; ch < nchunks; ch++) {
        const int s0 = ch * 64;
        __syncthreads();  // previous P@V (reads sV,sP) done before overwrite
        for (int idx = tid; idx < 64 * 192; idx += 256) {
            const int j = idx / 192, d = idx % 192;
            float v;
            if (d < 128) v = KV[(bT + s0 + j) * KVN + h * (NOPE + VD) + d];
            else         v = KR[(bT + s0 + j) * ROPE + (d - 128)];
            sK[j * QS + d] = v;
        }
        for (int idx = tid; idx < 64 * 128; idx += 256) {
            const int j = idx >> 7, c = idx & 127;
            sV[j * VS + c] = KV[(bT + s0 + j) * KVN + h * (NOPE + VD) + NOPE + c];
        }
        __syncthreads();

        // scores: 16 per thread, k-vectorized (1 Q LDS.128 amortized over 16 K rows)
        float sc[16];
#pragma unroll
        for (int jj = 0; jj < 16; jj++) sc[jj] = 0.f;
        const float4* q4 = (const float4*)(sQ + r * QS);
#pragma unroll 4
        for (int k = 0; k < 48; k++) {
            const float4 a = q4[k];
#pragma unroll
            for (int jj = 0; jj < 16; jj++) {
                const float4 bb = ((const float4*)(sK + (jg + jj) * QS))[k];
                sc[jj] = fmaf(a.x, bb.x, sc[jj]);
                sc[jj] = fmaf(a.y, bb.y, sc[jj]);
                sc[jj] = fmaf(a.z, bb.z, sc[jj]);
                sc[jj] = fmaf(a.w, bb.w, sc[jj]);
            }
        }
        float cm = -1e30f;
#pragma unroll
        for (int jj = 0; jj < 16; jj++) {
            float s = sc[jj] * SCALE;
            if (s0 + jg + jj > q0 + r) s = -1e30f;
            sc[jj] = s;
            cm = fmaxf(cm, s);
        }
        cm = fmaxf(cm, __shfl_xor_sync(0xffffffffu, cm, 1));
        cm = fmaxf(cm, __shfl_xor_sync(0xffffffffu, cm, 2));
        const float nm = fmaxf(m, cm);
        const float alpha = __expf(m - nm);
        float ls = 0.f;
#pragma unroll
        for (int jj = 0; jj < 16; jj++) {
            const float p = __expf(sc[jj] - nm);
            sP[r * PS + jg + jj] = p;
            ls += p;
        }
        ls += __shfl_xor_sync(0xffffffffu, ls, 1);
        ls += __shfl_xor_sync(0xffffffffu, ls, 2);
        l = l * alpha + ls;
        m = nm;
#pragma unroll
        for (int c = 0; c < 32; c++) acc[c] *= alpha;
        __syncthreads();

        // P @ V : each thread owns row r, cols [cbase, cbase+32)
        const float* pr = sP + r * PS;
        for (int j = 0; j < 64; j++) {
            const float p = pr[j];
            const float4* v4 = (const float4*)(sV + j * VS + cbase);
#pragma unroll
            for (int c4 = 0; c4 < 8; c4++) {
                const float4 v = v4[c4];
                acc[c4 * 4 + 0] = fmaf(p, v.x, acc[c4 * 4 + 0]);
                acc[c4 * 4 + 1] = fmaf(p, v.y, acc[c4 * 4 + 1]);
                acc[c4 * 4 + 2] = fmaf(p, v.z, acc[c4 * 4 + 2]);
                acc[c4 * 4 + 3] = fmaf(p, v.w, acc[c4 * 4 + 3]);
            }
        }
    }

    const float inv = 1.f / l;
    float* op = O + (bT + q0 + r) * (size_t)(H_ * VD) + h * VD + cbase;
#pragma unroll
    for (int c = 0; c < 32; c++) op[c] = acc[c] * inv;
}

// ---------------- host glue ----------------
static float* sym_addr(const void* symbol) {
    void* p = nullptr;
    cudaGetSymbolAddress(&p, symbol);
    return (float*)p;
}

extern "C" void kernel_launch(void* const* d_in, const int* in_sizes, int n_in,
                              void* d_out, int out_size)
{
    const float* hidden    = (const float*)d_in[0];
    const int*   positions = (const int*)  d_in[1];
    const float* w_qa  = (const float*)d_in[2];
    const float* g_qa  = (const float*)d_in[3];
    const float* w_qb  = (const float*)d_in[4];
    const float* w_kva = (const float*)d_in[5];
    const float* g_kva = (const float*)d_in[6];
    const float* w_kvb = (const float*)d_in[7];
    const float* w_o   = (const float*)d_in[8];

    float* out      = (float*)d_out;
    float* out_ckv  = out + (size_t)MT * D_;
    float* out_kr   = out_ckv + (size_t)MT * KVR;

    float* p_qlora = sym_addr(g_qlora);
    float* p_q     = sym_addr(g_q);
    float* p_kvc   = sym_addr(g_kvc);
    float* p_ckv   = sym_addr(g_ckv);
    float* p_kv    = sym_addr(g_kv);
    float* p_krope = sym_addr(g_krope);
    float* p_attn  = sym_addr(g_attn);

    static bool attr_set = false;
    if (!attr_set) {
        cudaFuncSetAttribute(attn_kernel, cudaFuncAttributeMaxDynamicSharedMemorySize,
                             ATTN_SMEM);
        attr_set = true;
    }

    dim3 blk(256);

    // 1) q_lora = x @ w_qa   (4096 x 768, K=2048)
    sgemm_kernel<<<dim3((QL + 127) / 128, MT / 128), blk>>>(hidden, w_qa, p_qlora, MT, QL, D_);
    // 2) rms in place
    rms_kernel<<<MT, blk>>>(p_qlora, g_qa, QL);
    // 3) q = qlora_n @ w_qb  (4096 x 3072, K=768)
    sgemm_kernel<<<dim3((QN + 127) / 128, MT / 128), blk>>>(p_qlora, w_qb, p_q, MT, QN, QL);
    // 4) kvc = x @ w_kva     (4096 x 576, K=2048)
    sgemm_kernel<<<dim3((KVR + ROPE + 127) / 128, MT / 128), blk>>>(hidden, w_kva, p_kvc, MT, KVR + ROPE, D_);
    // 5) rms(ckv) -> scratch + output; raw/roped k_rope -> output/scratch
    rmskv_rope_kernel<<<MT, blk>>>(p_kvc, g_kva, p_ckv, out_ckv, out_kr, p_krope);
    // 6) kv = ckv @ w_kvb    (4096 x 4096, K=512)
    sgemm_kernel<<<dim3(KVN / 128, MT / 128), blk>>>(p_ckv, w_kvb, p_kv, MT, KVN, KVR);
    // 7) rope q in place
    rope_q_kernel<<<MT, dim3(1024)>>>(p_q, positions);
    // 8) flash attention -> p_attn
    attn_kernel<<<dim3(T_ / 64, H_, B_), blk, ATTN_SMEM>>>(p_q, p_kv, p_krope, p_attn);
    // 9) output = attn @ w_o (4096 x 2048, K=2048)
    sgemm_kernel<<<dim3(D_ / 128, MT / 128), blk>>>(p_attn, w_o, out, MT, D_, D_);
}

// round 2
// speedup vs baseline: 3.1569x; 3.1569x over previous
#include <cuda_runtime.h>
#include <cuda_bf16.h>
#include <math.h>

// ---------------- problem constants ----------------
constexpr int B_   = 2;
constexpr int T_   = 2048;
constexpr int D_   = 2048;
constexpr int H_   = 16;
constexpr int NOPE = 128;
constexpr int ROPE = 64;
constexpr int QH   = NOPE + ROPE;          // 192
constexpr int QL   = H_ * QH / 4;          // 768
constexpr int KVR  = 512;
constexpr int VD   = 128;
constexpr int MT   = B_ * T_;              // 4096 rows
constexpr int KVN  = H_ * (NOPE + VD);     // 4096
constexpr int QN   = H_ * QH;              // 3072
constexpr float EPS = 1e-6f;
constexpr float SCALE = 0.07216878364870322f; // 192^-0.5

// ---------------- scratch (static device memory; no runtime alloc) ----------------
__device__ float g_qlora[(size_t)MT * QL];
__device__ float g_q[(size_t)MT * QN];
__device__ float g_kvc[(size_t)MT * (KVR + ROPE)];
__device__ float g_ckv[(size_t)MT * KVR];
__device__ float g_kv[(size_t)MT * KVN];
__device__ float g_krope[(size_t)MT * ROPE];
__device__ float g_attn[(size_t)MT * (H_ * VD)];

// ---------------- SGEMM: C = A(M,K) @ B(K,N), row-major, double-buffered ----------------
__global__ __launch_bounds__(256) void sgemm_kernel(
    const float* __restrict__ A, const float* __restrict__ Bm,
    float* __restrict__ C, int M, int N, int K)
{
    __shared__ float As[2][8][128];
    __shared__ float Bs[2][8][128];

    const int tid = threadIdx.x;
    const int m0 = blockIdx.y * 128;
    const int n0 = blockIdx.x * 128;
    const int tx = tid & 15;
    const int ty = tid >> 4;

    const int arow = tid >> 1;
    const int acol = (tid & 1) * 4;
    const int brow = tid >> 5;
    const int bcol = (tid & 31) * 4;
    const int bc   = n0 + bcol;

    float acc[8][8];
#pragma unroll
    for (int i = 0; i < 8; i++)
#pragma unroll
        for (int j = 0; j < 8; j++) acc[i][j] = 0.f;

    const int kTiles = K >> 3;

    // prologue: tile 0 into buffer 0
    {
        float4 av = *(const float4*)(A + (size_t)(m0 + arow) * K + acol);
        As[0][acol + 0][arow] = av.x;
        As[0][acol + 1][arow] = av.y;
        As[0][acol + 2][arow] = av.z;
        As[0][acol + 3][arow] = av.w;
        const float* bp = Bm + (size_t)brow * N + bc;
        float4 bv;
        if (bc + 3 < N) bv = *(const float4*)bp;
        else {
            bv.x = (bc + 0 < N) ? bp[0] : 0.f;
            bv.y = (bc + 1 < N) ? bp[1] : 0.f;
            bv.z = (bc + 2 < N) ? bp[2] : 0.f;
            bv.w = (bc + 3 < N) ? bp[3] : 0.f;
        }
        *(float4*)&Bs[0][brow][bcol] = bv;
    }
    __syncthreads();

    for (int kt = 0; kt < kTiles; kt++) {
        const int cur = kt & 1;
        const bool has_next = (kt + 1) < kTiles;
        float4 av, bv;
        if (has_next) {
            const int k0 = (kt + 1) * 8;
            av = *(const float4*)(A + (size_t)(m0 + arow) * K + k0 + acol);
            const float* bp = Bm + (size_t)(k0 + brow) * N + bc;
            if (bc + 3 < N) bv = *(const float4*)bp;
            else {
                bv.x = (bc + 0 < N) ? bp[0] : 0.f;
                bv.y = (bc + 1 < N) ? bp[1] : 0.f;
                bv.z = (bc + 2 < N) ? bp[2] : 0.f;
                bv.w = (bc + 3 < N) ? bp[3] : 0.f;
            }
        }
#pragma unroll
        for (int k = 0; k < 8; k++) {
            float4 a0 = *(const float4*)&As[cur][k][ty * 8];
            float4 a1 = *(const float4*)&As[cur][k][ty * 8 + 4];
            float4 b0 = *(const float4*)&Bs[cur][k][tx * 8];
            float4 b1 = *(const float4*)&Bs[cur][k][tx * 8 + 4];
            float ar[8] = {a0.x, a0.y, a0.z, a0.w, a1.x, a1.y, a1.z, a1.w};
            float br[8] = {b0.x, b0.y, b0.z, b0.w, b1.x, b1.y, b1.z, b1.w};
#pragma unroll
            for (int i = 0; i < 8; i++)
#pragma unroll
                for (int j = 0; j < 8; j++)
                    acc[i][j] = fmaf(ar[i], br[j], acc[i][j]);
        }
        if (has_next) {
            const int nxt = cur ^ 1;
            As[nxt][acol + 0][arow] = av.x;
            As[nxt][acol + 1][arow] = av.y;
            As[nxt][acol + 2][arow] = av.z;
            As[nxt][acol + 3][arow] = av.w;
            *(float4*)&Bs[nxt][brow][bcol] = bv;
        }
        __syncthreads();
    }
#pragma unroll
    for (int i = 0; i < 8; i++) {
        const int row = m0 + ty * 8 + i;
        float* cp = C + (size_t)row * N + n0 + tx * 8;
#pragma unroll
        for (int j = 0; j < 8; j++) {
            const int col = n0 + tx * 8 + j;
            if (col < N) cp[j] = acc[i][j];
        }
    }
}

// ---------------- block reduce (sum) ----------------
__device__ __forceinline__ float block_sum(float v) {
    __shared__ float red[8];
    __shared__ float tot;
    const int lane = threadIdx.x & 31, w = threadIdx.x >> 5;
#pragma unroll
    for (int o = 16; o; o >>= 1) v += __shfl_xor_sync(0xffffffffu, v, o);
    if (lane == 0) red[w] = v;
    __syncthreads();
    if (w == 0) {
        float x = (threadIdx.x < (blockDim.x >> 5)) ? red[threadIdx.x] : 0.f;
#pragma unroll
        for (int o = 4; o; o >>= 1) x += __shfl_xor_sync(0xffffffffu, x, o);
        if (threadIdx.x == 0) tot = x;
    }
    __syncthreads();
    return tot;
}

// ---------------- RMSNorm (in place) ----------------
__global__ __launch_bounds__(256) void rms_kernel(
    float* __restrict__ X, const float* __restrict__ g, int ncols)
{
    const int row = blockIdx.x;
    float* x = X + (size_t)row * ncols;
    float ss = 0.f;
    for (int c = threadIdx.x; c < ncols; c += blockDim.x) { float v = x[c]; ss += v * v; }
    const float total = block_sum(ss);
    const float rs = rsqrtf(total / (float)ncols + EPS);
    for (int c = threadIdx.x; c < ncols; c += blockDim.x)
        x[c] = x[c] * rs * g[c];
}

// ---------------- kv path: rms(c_kv) -> outputs; split + rope k ----------------
__global__ __launch_bounds__(256) void rmskv_rope_kernel(
    const float* __restrict__ kvc, const float* __restrict__ g_kva_,
    float* __restrict__ ckv_scr, float* __restrict__ out_ckv,
    float* __restrict__ out_kr, float* __restrict__ kr_rot)
{
    const int row = blockIdx.x;
    const int t = row % T_;
    const float* x = kvc + (size_t)row * (KVR + ROPE);
    float ss = 0.f;
    for (int c = threadIdx.x; c < KVR; c += blockDim.x) { float v = x[c]; ss += v * v; }
    const float total = block_sum(ss);
    const float rs = rsqrtf(total / (float)KVR + EPS);
    for (int c = threadIdx.x; c < KVR; c += blockDim.x) {
        const float v = x[c] * rs * g_kva_[c];
        ckv_scr[(size_t)row * KVR + c] = v;
        out_ckv[(size_t)row * KVR + c] = v;
    }
    if (threadIdx.x < ROPE) {
        const int d = threadIdx.x;
        const float raw = x[KVR + d];
        out_kr[(size_t)row * ROPE + d] = raw;
        const int j = d & 31;
        const float inv = powf(10000.f, -(float)(2 * j) / (float)ROPE);
        const float fr = (float)t * inv;
        const float other = (d < 32) ? -x[KVR + d + 32] : x[KVR + d - 32];
        kr_rot[(size_t)row * ROPE + d] = raw * cosf(fr) + other * sinf(fr);
    }
}

// ---------------- rope for q (in place in g_q) ----------------
__global__ __launch_bounds__(1024) void rope_q_kernel(
    float* __restrict__ q, const int* __restrict__ positions)
{
    const int row = blockIdx.x;
    const int pos = positions[row];
    const int h = threadIdx.x >> 6;
    const int d = threadIdx.x & 63;
    float* qr = q + (size_t)row * QN + h * QH + NOPE;
    const float xv = qr[d];
    const float other = (d < 32) ? -qr[d + 32] : qr[d - 32];
    __syncthreads();
    const int j = d & 31;
    const float inv = powf(10000.f, -(float)(2 * j) / (float)ROPE);
    const float fr = (float)pos * inv;
    qr[d] = xv * cosf(fr) + other * sinf(fr);
}

// ---------------- flash attention, register-blocked ----------------
// grid (T/64, H, B), 256 threads. BM=BN=64.
// Score tile: thread (ti,tj) owns rows ti*4+ii (ii<4), cols tj+16*jj (jj<4).
// Output tile: rows ti*4+ii, cols tj*8+c (c<8).
constexpr int QS = 196;   // pitch for 192-wide Q/K tiles (float4-aligned)
constexpr int VS = 132;   // pitch for 128-wide V tile
constexpr int PS = 68;    // pitch for 64-wide P tile
constexpr int ATTN_SMEM = (64 * QS * 2 + 64 * VS + 64 * PS) * 4; // 151552 bytes

__global__ __launch_bounds__(256) void attn_kernel(
    const float* __restrict__ Q, const float* __restrict__ KV,
    const float* __restrict__ KR, float* __restrict__ O)
{
    extern __shared__ float sm[];
    float* sQ = sm;
    float* sK = sQ + 64 * QS;
    float* sV = sK + 64 * QS;
    float* sP = sV + 64 * VS;

    const int qt = blockIdx.x;
    const int h  = blockIdx.y;
    const int b  = blockIdx.z;
    const int q0 = qt * 64;
    const size_t bT = (size_t)b * T_;
    const int tid = threadIdx.x;

    const int ti = tid >> 4;       // 0..15
    const int tj = tid & 15;       // 0..15
    const int r0 = ti * 4;         // base score/output row

    // ---- load Q tile 64x192 (float4 groups) ----
    for (int idx = tid; idx < 64 * 48; idx += 256) {
        const int j = idx / 48, dg = idx % 48;
        const float4 v = *(const float4*)(Q + (bT + q0 + j) * QN + h * QH + dg * 4);
        *(float4*)&sQ[j * QS + dg * 4] = v;
    }

    float m[4], l[4];
    float acc[4][8];
#pragma unroll
    for (int ii = 0; ii < 4; ii++) {
        m[ii] = -1e30f; l[ii] = 0.f;
#pragma unroll
        for (int c = 0; c < 8; c++) acc[ii][c] = 0.f;
    }
    __syncthreads();

    const int nchunks = qt + 1;
    for (int ch = 0; ch < nchunks; ch++) {
        const int s0 = ch * 64;
        __syncthreads();  // previous iteration's reads of sK/sV/sP complete
        // ---- load K tile 64x192 (nope from KV, rope from KR) ----
        for (int idx = tid; idx < 64 * 48; idx += 256) {
            const int j = idx / 48, dg = idx % 48;
            float4 v;
            if (dg < 32) v = *(const float4*)(KV + (bT + s0 + j) * KVN + h * (NOPE + VD) + dg * 4);
            else         v = *(const float4*)(KR + (bT + s0 + j) * ROPE + (dg - 32) * 4);
            *(float4*)&sK[j * QS + dg * 4] = v;
        }
        // ---- load V tile 64x128 ----
        for (int idx = tid; idx < 64 * 32; idx += 256) {
            const int j = idx >> 5, c4 = idx & 31;
            const float4 v = *(const float4*)(KV + (bT + s0 + j) * KVN + h * (NOPE + VD) + NOPE + c4 * 4);
            *(float4*)&sV[j * VS + c4 * 4] = v;
        }
        __syncthreads();

        // ---- scores: 4x4 micro-tile, inner product over 192 dims ----
        float sc[4][4];
#pragma unroll
        for (int ii = 0; ii < 4; ii++)
#pragma unroll
            for (int jj = 0; jj < 4; jj++) sc[ii][jj] = 0.f;

#pragma unroll 4
        for (int k4 = 0; k4 < 48; k4++) {
            float4 qa[4], kb[4];
#pragma unroll
            for (int ii = 0; ii < 4; ii++)
                qa[ii] = *(const float4*)&sQ[(r0 + ii) * QS + k4 * 4];
#pragma unroll
            for (int jj = 0; jj < 4; jj++)
                kb[jj] = *(const float4*)&sK[(tj + 16 * jj) * QS + k4 * 4];
#pragma unroll
            for (int ii = 0; ii < 4; ii++)
#pragma unroll
                for (int jj = 0; jj < 4; jj++) {
                    sc[ii][jj] = fmaf(qa[ii].x, kb[jj].x, sc[ii][jj]);
                    sc[ii][jj] = fmaf(qa[ii].y, kb[jj].y, sc[ii][jj]);
                    sc[ii][jj] = fmaf(qa[ii].z, kb[jj].z, sc[ii][jj]);
                    sc[ii][jj] = fmaf(qa[ii].w, kb[jj].w, sc[ii][jj]);
                }
        }

        // ---- scale + mask (diagonal chunk only) ----
        const bool diag = (ch == qt);
#pragma unroll
        for (int ii = 0; ii < 4; ii++)
#pragma unroll
            for (int jj = 0; jj < 4; jj++) {
                float s = sc[ii][jj] * SCALE;
                if (diag && (tj + 16 * jj > r0 + ii)) s = -1e30f;
                sc[ii][jj] = s;
            }

        // ---- online softmax ----
        float rmax[4], rsum[4];
#pragma unroll
        for (int ii = 0; ii < 4; ii++) {
            float v = fmaxf(fmaxf(sc[ii][0], sc[ii][1]), fmaxf(sc[ii][2], sc[ii][3]));
#pragma unroll
            for (int o = 1; o < 16; o <<= 1) v = fmaxf(v, __shfl_xor_sync(0xffffffffu, v, o));
            rmax[ii] = v;
        }
        float alpha[4];
#pragma unroll
        for (int ii = 0; ii < 4; ii++) {
            const float nm = fmaxf(m[ii], rmax[ii]);
            alpha[ii] = __expf(m[ii] - nm);
            float s = 0.f;
#pragma unroll
            for (int jj = 0; jj < 4; jj++) {
                const float p = __expf(sc[ii][jj] - nm);
                sP[(r0 + ii) * PS + tj + 16 * jj] = p;
                s += p;
            }
            rsum[ii] = s;
            m[ii] = nm;
        }
#pragma unroll
        for (int ii = 0; ii < 4; ii++) {
            float v = rsum[ii];
#pragma unroll
            for (int o = 1; o < 16; o <<= 1) v += __shfl_xor_sync(0xffffffffu, v, o);
            l[ii] = l[ii] * alpha[ii] + v;
#pragma unroll
            for (int c = 0; c < 8; c++) acc[ii][c] *= alpha[ii];
        }
        __syncthreads();  // sP fully written

        // ---- P @ V : 4x8 micro-tile ----
#pragma unroll 2
        for (int j = 0; j < 64; j++) {
            float pr[4];
#pragma unroll
            for (int ii = 0; ii < 4; ii++) pr[ii] = sP[(r0 + ii) * PS + j];
            const float4 v0 = *(const float4*)&sV[j * VS + tj * 8];
            const float4 v1 = *(const float4*)&sV[j * VS + tj * 8 + 4];
#pragma unroll
            for (int ii = 0; ii < 4; ii++) {
                acc[ii][0] = fmaf(pr[ii], v0.x, acc[ii][0]);
                acc[ii][1] = fmaf(pr[ii], v0.y, acc[ii][1]);
                acc[ii][2] = fmaf(pr[ii], v0.z, acc[ii][2]);
                acc[ii][3] = fmaf(pr[ii], v0.w, acc[ii][3]);
                acc[ii][4] = fmaf(pr[ii], v1.x, acc[ii][4]);
                acc[ii][5] = fmaf(pr[ii], v1.y, acc[ii][5]);
                acc[ii][6] = fmaf(pr[ii], v1.z, acc[ii][6]);
                acc[ii][7] = fmaf(pr[ii], v1.w, acc[ii][7]);
            }
        }
    }

#pragma unroll
    for (int ii = 0; ii < 4; ii++) {
        const float inv = 1.f / l[ii];
        float* op = O + (bT + q0 + r0 + ii) * (size_t)(H_ * VD) + h * VD + tj * 8;
#pragma unroll
        for (int c = 0; c < 8; c++) op[c] = acc[ii][c] * inv;
    }
}

// ---------------- host glue ----------------
static float* sym_addr(const void* symbol) {
    void* p = nullptr;
    cudaGetSymbolAddress(&p, symbol);
    return (float*)p;
}

extern "C" void kernel_launch(void* const* d_in, const int* in_sizes, int n_in,
                              void* d_out, int out_size)
{
    const float* hidden    = (const float*)d_in[0];
    const int*   positions = (const int*)  d_in[1];
    const float* w_qa  = (const float*)d_in[2];
    const float* g_qa  = (const float*)d_in[3];
    const float* w_qb  = (const float*)d_in[4];
    const float* w_kva = (const float*)d_in[5];
    const float* g_kva = (const float*)d_in[6];
    const float* w_kvb = (const float*)d_in[7];
    const float* w_o   = (const float*)d_in[8];

    float* out      = (float*)d_out;
    float* out_ckv  = out + (size_t)MT * D_;
    float* out_kr   = out_ckv + (size_t)MT * KVR;

    float* p_qlora = sym_addr(g_qlora);
    float* p_q     = sym_addr(g_q);
    float* p_kvc   = sym_addr(g_kvc);
    float* p_ckv   = sym_addr(g_ckv);
    float* p_kv    = sym_addr(g_kv);
    float* p_krope = sym_addr(g_krope);
    float* p_attn  = sym_addr(g_attn);

    static bool attr_set = false;
    if (!attr_set) {
        cudaFuncSetAttribute(attn_kernel, cudaFuncAttributeMaxDynamicSharedMemorySize,
                             ATTN_SMEM);
        attr_set = true;
    }

    dim3 blk(256);

    sgemm_kernel<<<dim3((QL + 127) / 128, MT / 128), blk>>>(hidden, w_qa, p_qlora, MT, QL, D_);
    rms_kernel<<<MT, blk>>>(p_qlora, g_qa, QL);
    sgemm_kernel<<<dim3((QN + 127) / 128, MT / 128), blk>>>(p_qlora, w_qb, p_q, MT, QN, QL);
    sgemm_kernel<<<dim3((KVR + ROPE + 127) / 128, MT / 128), blk>>>(hidden, w_kva, p_kvc, MT, KVR + ROPE, D_);
    rmskv_rope_kernel<<<MT, blk>>>(p_kvc, g_kva, p_ckv, out_ckv, out_kr, p_krope);
    sgemm_kernel<<<dim3(KVN / 128, MT / 128), blk>>>(p_ckv, w_kvb, p_kv, MT, KVN, KVR);
    rope_q_kernel<<<MT, dim3(1024)>>>(p_q, positions);
    attn_kernel<<<dim3(T_ / 64, H_, B_), blk, ATTN_SMEM>>>(p_q, p_kv, p_krope, p_attn);
    sgemm_kernel<<<dim3(D_ / 128, MT / 128), blk>>>(p_attn, w_o, out, MT, D_, D_);
}

// round 4
// speedup vs baseline: 5.2383x; 1.6593x over previous
#include <cuda_runtime.h>
#include <cuda_bf16.h>
#include <math.h>
#include <stdint.h>

// ---------------- problem constants ----------------
constexpr int B_   = 2;
constexpr int T_   = 2048;
constexpr int D_   = 2048;
constexpr int H_   = 16;
constexpr int NOPE = 128;
constexpr int ROPE = 64;
constexpr int QH   = NOPE + ROPE;          // 192
constexpr int QL   = H_ * QH / 4;          // 768
constexpr int KVR  = 512;
constexpr int VD   = 128;
constexpr int MT   = B_ * T_;              // 4096 rows
constexpr int KVN  = H_ * (NOPE + VD);     // 4096
constexpr int QN   = H_ * QH;              // 3072
constexpr int KVC  = KVR + ROPE;           // 576
constexpr int KVCP = 640;                  // padded to 128
constexpr float EPS = 1e-6f;
constexpr float SCALE = 0.07216878364870322f; // 192^-0.5

// ---------------- static scratch ----------------
__device__ float g_qlora[(size_t)MT * QL];
__device__ float g_q[(size_t)MT * QN];
__device__ float g_kvc[(size_t)MT * KVC];
__device__ float g_kv[(size_t)MT * KVN];
__device__ float g_krope[(size_t)MT * ROPE];

__device__ __nv_bfloat16 hid_h[(size_t)MT * D_],  hid_l[(size_t)MT * D_];
__device__ __nv_bfloat16 qlo_h[(size_t)MT * QL],  qlo_l[(size_t)MT * QL];
__device__ __nv_bfloat16 ckv_h[(size_t)MT * KVR], ckv_l[(size_t)MT * KVR];
__device__ __nv_bfloat16 atn_h[(size_t)MT * D_],  atn_l[(size_t)MT * D_];

__device__ __nv_bfloat16 wqaT_h[(size_t)QL * D_],    wqaT_l[(size_t)QL * D_];
__device__ __nv_bfloat16 wqbT_h[(size_t)QN * QL],    wqbT_l[(size_t)QN * QL];
__device__ __nv_bfloat16 wkvaT_h[(size_t)KVCP * D_], wkvaT_l[(size_t)KVCP * D_];
__device__ __nv_bfloat16 wkvbT_h[(size_t)KVN * KVR], wkvbT_l[(size_t)KVN * KVR];
__device__ __nv_bfloat16 woT_h[(size_t)D_ * D_],     woT_l[(size_t)D_ * D_];

// ---------------- PTX helpers (sm_80-class only; no tcgen05) ----------------
__device__ __forceinline__ uint32_t smem_u32(const void* p) {
    uint32_t a;
    asm("{ .reg .u64 t; cvta.to.shared.u64 t, %1; cvt.u32.u64 %0, t; }"
        : "=r"(a) : "l"(p));
    return a;
}
__device__ __forceinline__ void split2(float x, __nv_bfloat16& h, __nv_bfloat16& l) {
    h = __float2bfloat16(x);
    l = __float2bfloat16(x - __bfloat162float(h));
}
__device__ __forceinline__ void cp16(uint32_t dst, const void* src) {
    asm volatile("cp.async.cg.shared.global [%0], [%1], 16;"
                 :: "r"(dst), "l"(src) : "memory");
}
__device__ __forceinline__ void ldm4(uint32_t* r, uint32_t a) {
    asm volatile("ldmatrix.sync.aligned.m8n8.x4.shared.b16 {%0,%1,%2,%3}, [%4];"
                 : "=r"(r[0]), "=r"(r[1]), "=r"(r[2]), "=r"(r[3]) : "r"(a));
}
__device__ __forceinline__ void ldm2(uint32_t* r, uint32_t a) {
    asm volatile("ldmatrix.sync.aligned.m8n8.x2.shared.b16 {%0,%1}, [%2];"
                 : "=r"(r[0]), "=r"(r[1]) : "r"(a));
}
__device__ __forceinline__ void mma16816(float* d, const uint32_t* a, const uint32_t* b) {
    asm volatile(
        "mma.sync.aligned.m16n8k16.row.col.f32.bf16.bf16.f32 "
        "{%0,%1,%2,%3}, {%4,%5,%6,%7}, {%8,%9}, {%0,%1,%2,%3};"
        : "+f"(d[0]), "+f"(d[1]), "+f"(d[2]), "+f"(d[3])
        : "r"(a[0]), "r"(a[1]), "r"(a[2]), "r"(a[3]), "r"(b[0]), "r"(b[1]));
}

// ---------------- split-bf16 HMMA GEMM ----------------
// C(M,N) fp32 = (Ah+Al)(M,K) @ (Bh+Bl)^T ; A [M,K], B stored [Npad,K] bf16.
// 128x128 tile, BK=32, 256 threads (8 warps, 2x4), warp tile 64x32.
// smem: per stage {Ah,Al,Bh,Bl} 8KB each = 32KB; double buffered = 64KB.
constexpr int GSMEM = 65536;

__global__ __launch_bounds__(256) void mmagemm_kernel(
    const __nv_bfloat16* __restrict__ Ah, const __nv_bfloat16* __restrict__ Al,
    const __nv_bfloat16* __restrict__ Bh, const __nv_bfloat16* __restrict__ Bl,
    float* __restrict__ C, int M, int N, int K)
{
    extern __shared__ char smraw[];
    const uint32_t sbase0 = smem_u32(smraw);

    const int tid = threadIdx.x, lane = tid & 31, wid = tid >> 5;
    const int wm = wid >> 2, wn = wid & 3;
    const int m0 = blockIdx.y * 128, n0 = blockIdx.x * 128;
    const int KT = K >> 5;

    float acc[4][4][4];
#pragma unroll
    for (int i = 0; i < 4; i++)
#pragma unroll
        for (int j = 0; j < 4; j++)
#pragma unroll
            for (int q = 0; q < 4; q++) acc[i][j][q] = 0.f;

    // per-thread load slots: 512 chunks per array, 2 per thread
    const int lrow0 = tid >> 2, lc0 = tid & 3;           // g = tid
    const int lrow1 = (tid + 256) >> 2, lc1 = (tid + 256) & 3;

    auto load_stage = [&](int buf, int kc) {
        const uint32_t sb = sbase0 + buf * 32768;
        {
            const uint32_t cp_ = (uint32_t)(lc0 ^ ((lrow0 & 7) >> 1));
            const uint32_t off = (uint32_t)lrow0 * 64u + cp_ * 16u;
            const size_t ga = (size_t)(m0 + lrow0) * K + kc + lc0 * 8;
            const size_t gb = (size_t)(n0 + lrow0) * K + kc + lc0 * 8;
            cp16(sb + off,          Ah + ga);
            cp16(sb + 8192 + off,   Al + ga);
            cp16(sb + 16384 + off,  Bh + gb);
            cp16(sb + 24576 + off,  Bl + gb);
        }
        {
            const uint32_t cp_ = (uint32_t)(lc1 ^ ((lrow1 & 7) >> 1));
            const uint32_t off = (uint32_t)lrow1 * 64u + cp_ * 16u;
            const size_t ga = (size_t)(m0 + lrow1) * K + kc + lc1 * 8;
            const size_t gb = (size_t)(n0 + lrow1) * K + kc + lc1 * 8;
            cp16(sb + off,          Ah + ga);
            cp16(sb + 8192 + off,   Al + ga);
            cp16(sb + 16384 + off,  Bh + gb);
            cp16(sb + 24576 + off,  Bl + gb);
        }
        asm volatile("cp.async.commit_group;" ::: "memory");
    };

    load_stage(0, 0);

    for (int kt = 0; kt < KT; kt++) {
        const int buf = kt & 1;
        if (kt + 1 < KT) {
            load_stage(buf ^ 1, (kt + 1) * 32);
            asm volatile("cp.async.wait_group 1;" ::: "memory");
        } else {
            asm volatile("cp.async.wait_group 0;" ::: "memory");
        }
        __syncthreads();

        const uint32_t aAh = sbase0 + buf * 32768;
        const uint32_t aAl = aAh + 8192;
        const uint32_t aBh = aAh + 16384;
        const uint32_t aBl = aAh + 24576;

#pragma unroll
        for (int ks = 0; ks < 2; ks++) {
            uint32_t fAh[4][4], fAl[4][4], fBh[4][2], fBl[4][2];
#pragma unroll
            for (int mf = 0; mf < 4; mf++) {
                const int row = wm * 64 + mf * 16 + (lane & 15);
                const int c = ks * 2 + (lane >> 4);
                const uint32_t off = (uint32_t)row * 64u
                                   + (uint32_t)((c ^ ((row & 7) >> 1)) * 16);
                ldm4(fAh[mf], aAh + off);
                ldm4(fAl[mf], aAl + off);
            }
#pragma unroll
            for (int nf = 0; nf < 4; nf++) {
                const int row = wn * 32 + nf * 8 + (lane & 7);
                const int c = ks * 2 + ((lane >> 3) & 1);
                const uint32_t off = (uint32_t)row * 64u
                                   + (uint32_t)((c ^ ((row & 7) >> 1)) * 16);
                ldm2(fBh[nf], aBh + off);
                ldm2(fBl[nf], aBl + off);
            }
#pragma unroll
            for (int mf = 0; mf < 4; mf++)
#pragma unroll
                for (int nf = 0; nf < 4; nf++)
                    mma16816(acc[mf][nf], fAh[mf], fBh[nf]);
#pragma unroll
            for (int mf = 0; mf < 4; mf++)
#pragma unroll
                for (int nf = 0; nf < 4; nf++)
                    mma16816(acc[mf][nf], fAl[mf], fBh[nf]);
#pragma unroll
            for (int mf = 0; mf < 4; mf++)
#pragma unroll
                for (int nf = 0; nf < 4; nf++)
                    mma16816(acc[mf][nf], fAh[mf], fBl[nf]);
        }
        __syncthreads();
    }

    // epilogue
    const int g = lane >> 2, tq = lane & 3;
#pragma unroll
    for (int mf = 0; mf < 4; mf++) {
        const int row = m0 + wm * 64 + mf * 16 + g;
#pragma unroll
        for (int nf = 0; nf < 4; nf++) {
            const int col = n0 + wn * 32 + nf * 8 + tq * 2;
            if (col < N) {
                float2 v0 = make_float2(acc[mf][nf][0], acc[mf][nf][1]);
                float2 v1 = make_float2(acc[mf][nf][2], acc[mf][nf][3]);
                *(float2*)(C + (size_t)row * N + col) = v0;
                *(float2*)(C + (size_t)(row + 8) * N + col) = v1;
            }
        }
    }
}

// ---------------- weight transpose + hi/lo split ----------------
// W [K,N] fp32 -> Th/Tl [Npad,K] bf16 (rows >= N zero-filled)
__global__ __launch_bounds__(256) void transpose_split_kernel(
    const float* __restrict__ W, __nv_bfloat16* __restrict__ Th,
    __nv_bfloat16* __restrict__ Tl, int K, int N)
{
    __shared__ float t[32][33];
    const int tx = threadIdx.x & 31, ty = threadIdx.x >> 5;
    const int n0 = blockIdx.x * 32, k0 = blockIdx.y * 32;
#pragma unroll
    for (int i = 0; i < 4; i++) {
        const int k = k0 + ty + i * 8, n = n0 + tx;
        t[ty + i * 8][tx] = (n < N) ? W[(size_t)k * N + n] : 0.f;
    }
    __syncthreads();
#pragma unroll
    for (int i = 0; i < 4; i++) {
        const int n = n0 + ty + i * 8, k = k0 + tx;
        __nv_bfloat16 h, l;
        split2(t[tx][ty + i * 8], h, l);
        Th[(size_t)n * K + k] = h;
        Tl[(size_t)n * K + k] = l;
    }
}

// ---------------- elementwise fp32 -> hi/lo bf16 ----------------
__global__ __launch_bounds__(256) void split_kernel(
    const float* __restrict__ X, __nv_bfloat16* __restrict__ H,
    __nv_bfloat16* __restrict__ L, size_t n)
{
    const size_t i = (size_t)blockIdx.x * blockDim.x + threadIdx.x;
    if (i < n) {
        __nv_bfloat16 h, l;
        split2(X[i], h, l);
        H[i] = h; L[i] = l;
    }
}

// ---------------- block reduce ----------------
__device__ __forceinline__ float block_sum(float v) {
    __shared__ float red[8];
    __shared__ float tot;
    const int lane = threadIdx.x & 31, w = threadIdx.x >> 5;
#pragma unroll
    for (int o = 16; o; o >>= 1) v += __shfl_xor_sync(0xffffffffu, v, o);
    if (lane == 0) red[w] = v;
    __syncthreads();
    if (w == 0) {
        float x = (threadIdx.x < (blockDim.x >> 5)) ? red[threadIdx.x] : 0.f;
#pragma unroll
        for (int o = 4; o; o >>= 1) x += __shfl_xor_sync(0xffffffffu, x, o);
        if (threadIdx.x == 0) tot = x;
    }
    __syncthreads();
    return tot;
}

// ---------------- RMSNorm -> hi/lo bf16 ----------------
__global__ __launch_bounds__(256) void rms_split_kernel(
    const float* __restrict__ X, const float* __restrict__ g, int ncols,
    __nv_bfloat16* __restrict__ Oh, __nv_bfloat16* __restrict__ Ol)
{
    const int row = blockIdx.x;
    const float* x = X + (size_t)row * ncols;
    float ss = 0.f;
    for (int c = threadIdx.x; c < ncols; c += blockDim.x) { float v = x[c]; ss += v * v; }
    const float total = block_sum(ss);
    const float rs = rsqrtf(total / (float)ncols + EPS);
    for (int c = threadIdx.x; c < ncols; c += blockDim.x) {
        __nv_bfloat16 h, l;
        split2(x[c] * rs * g[c], h, l);
        Oh[(size_t)row * ncols + c] = h;
        Ol[(size_t)row * ncols + c] = l;
    }
}

// ---------------- kv path: rms(c_kv) + rope(k) ----------------
__global__ __launch_bounds__(256) void rmskv_rope_kernel(
    const float* __restrict__ kvc, const float* __restrict__ g_kva_,
    float* __restrict__ out_ckv, __nv_bfloat16* __restrict__ ch,
    __nv_bfloat16* __restrict__ cl, float* __restrict__ out_kr,
    float* __restrict__ kr_rot)
{
    const int row = blockIdx.x;
    const int t = row % T_;
    const float* x = kvc + (size_t)row * KVC;
    float ss = 0.f;
    for (int c = threadIdx.x; c < KVR; c += blockDim.x) { float v = x[c]; ss += v * v; }
    const float total = block_sum(ss);
    const float rs = rsqrtf(total / (float)KVR + EPS);
    for (int c = threadIdx.x; c < KVR; c += blockDim.x) {
        const float v = x[c] * rs * g_kva_[c];
        out_ckv[(size_t)row * KVR + c] = v;
        __nv_bfloat16 h, l;
        split2(v, h, l);
        ch[(size_t)row * KVR + c] = h;
        cl[(size_t)row * KVR + c] = l;
    }
    if (threadIdx.x < ROPE) {
        const int d = threadIdx.x;
        const float raw = x[KVR + d];
        out_kr[(size_t)row * ROPE + d] = raw;
        const int j = d & 31;
        const float inv = powf(10000.f, -(float)(2 * j) / (float)ROPE);
        const float fr = (float)t * inv;
        const float other = (d < 32) ? -x[KVR + d + 32] : x[KVR + d - 32];
        kr_rot[(size_t)row * ROPE + d] = raw * cosf(fr) + other * sinf(fr);
    }
}

// ---------------- rope for q (in place) ----------------
__global__ __launch_bounds__(1024) void rope_q_kernel(
    float* __restrict__ q, const int* __restrict__ positions)
{
    const int row = blockIdx.x;
    const int pos = positions[row];
    const int h = threadIdx.x >> 6;
    const int d = threadIdx.x & 63;
    float* qr = q + (size_t)row * QN + h * QH + NOPE;
    const float xv = qr[d];
    const float other = (d < 32) ? -qr[d + 32] : qr[d - 32];
    __syncthreads();
    const int j = d & 31;
    const float inv = powf(10000.f, -(float)(2 * j) / (float)ROPE);
    const float fr = (float)pos * inv;
    qr[d] = xv * cosf(fr) + other * sinf(fr);
}

// ---------------- flash attention (fp32, register-blocked) ----------------
constexpr int QS = 196;
constexpr int VS = 132;
constexpr int PS = 68;
constexpr int ATTN_SMEM = (64 * QS * 2 + 64 * VS + 64 * PS) * 4;

__global__ __launch_bounds__(256) void attn_kernel(
    const float* __restrict__ Q, const float* __restrict__ KV,
    const float* __restrict__ KR, __nv_bfloat16* __restrict__ Oh,
    __nv_bfloat16* __restrict__ Ol)
{
    extern __shared__ float sm[];
    float* sQ = sm;
    float* sK = sQ + 64 * QS;
    float* sV = sK + 64 * QS;
    float* sP = sV + 64 * VS;

    const int qt = blockIdx.x;
    const int h  = blockIdx.y;
    const int b  = blockIdx.z;
    const int q0 = qt * 64;
    const size_t bT = (size_t)b * T_;
    const int tid = threadIdx.x;

    const int ti = tid >> 4;
    const int tj = tid & 15;
    const int r0 = ti * 4;

    for (int idx = tid; idx < 64 * 48; idx += 256) {
        const int j = idx / 48, dg = idx % 48;
        const float4 v = *(const float4*)(Q + (bT + q0 + j) * QN + h * QH + dg * 4);
        *(float4*)&sQ[j * QS + dg * 4] = v;
    }

    float m[4], l[4];
    float acc[4][8];
#pragma unroll
    for (int ii = 0; ii < 4; ii++) {
        m[ii] = -1e30f; l[ii] = 0.f;
#pragma unroll
        for (int c = 0; c < 8; c++) acc[ii][c] = 0.f;
    }
    __syncthreads();

    const int nchunks = qt + 1;
    for (int ch = 0; ch < nchunks; ch++) {
        const int s0 = ch * 64;
        __syncthreads();
        for (int idx = tid; idx < 64 * 48; idx += 256) {
            const int j = idx / 48, dg = idx % 48;
            float4 v;
            if (dg < 32) v = *(const float4*)(KV + (bT + s0 + j) * KVN + h * (NOPE + VD) + dg * 4);
            else         v = *(const float4*)(KR + (bT + s0 + j) * ROPE + (dg - 32) * 4);
            *(float4*)&sK[j * QS + dg * 4] = v;
        }
        for (int idx = tid; idx < 64 * 32; idx += 256) {
            const int j = idx >> 5, c4 = idx & 31;
            const float4 v = *(const float4*)(KV + (bT + s0 + j) * KVN + h * (NOPE + VD) + NOPE + c4 * 4);
            *(float4*)&sV[j * VS + c4 * 4] = v;
        }
        __syncthreads();

        float sc[4][4];
#pragma unroll
        for (int ii = 0; ii < 4; ii++)
#pragma unroll
            for (int jj = 0; jj < 4; jj++) sc[ii][jj] = 0.f;

#pragma unroll 4
        for (int k4 = 0; k4 < 48; k4++) {
            float4 qa[4], kb[4];
#pragma unroll
            for (int ii = 0; ii < 4; ii++)
                qa[ii] = *(const float4*)&sQ[(r0 + ii) * QS + k4 * 4];
#pragma unroll
            for (int jj = 0; jj < 4; jj++)
                kb[jj] = *(const float4*)&sK[(tj + 16 * jj) * QS + k4 * 4];
#pragma unroll
            for (int ii = 0; ii < 4; ii++)
#pragma unroll
                for (int jj = 0; jj < 4; jj++) {
                    sc[ii][jj] = fmaf(qa[ii].x, kb[jj].x, sc[ii][jj]);
                    sc[ii][jj] = fmaf(qa[ii].y, kb[jj].y, sc[ii][jj]);
                    sc[ii][jj] = fmaf(qa[ii].z, kb[jj].z, sc[ii][jj]);
                    sc[ii][jj] = fmaf(qa[ii].w, kb[jj].w, sc[ii][jj]);
                }
        }

        const bool diag = (ch == qt);
#pragma unroll
        for (int ii = 0; ii < 4; ii++)
#pragma unroll
            for (int jj = 0; jj < 4; jj++) {
                float s = sc[ii][jj] * SCALE;
                if (diag && (tj + 16 * jj > r0 + ii)) s = -1e30f;
                sc[ii][jj] = s;
            }

        float rmax[4], rsum[4];
#pragma unroll
        for (int ii = 0; ii < 4; ii++) {
            float v = fmaxf(fmaxf(sc[ii][0], sc[ii][1]), fmaxf(sc[ii][2], sc[ii][3]));
#pragma unroll
            for (int o = 1; o < 16; o <<= 1) v = fmaxf(v, __shfl_xor_sync(0xffffffffu, v, o));
            rmax[ii] = v;
        }
        float alpha[4];
#pragma unroll
        for (int ii = 0; ii < 4; ii++) {
            const float nm = fmaxf(m[ii], rmax[ii]);
            alpha[ii] = __expf(m[ii] - nm);
            float s = 0.f;
#pragma unroll
            for (int jj = 0; jj < 4; jj++) {
                const float p = __expf(sc[ii][jj] - nm);
                sP[(r0 + ii) * PS + tj + 16 * jj] = p;
                s += p;
            }
            rsum[ii] = s;
            m[ii] = nm;
        }
#pragma unroll
        for (int ii = 0; ii < 4; ii++) {
            float v = rsum[ii];
#pragma unroll
            for (int o = 1; o < 16; o <<= 1) v += __shfl_xor_sync(0xffffffffu, v, o);
            l[ii] = l[ii] * alpha[ii] + v;
#pragma unroll
            for (int c = 0; c < 8; c++) acc[ii][c] *= alpha[ii];
        }
        __syncthreads();

#pragma unroll 2
        for (int j = 0; j < 64; j++) {
            float pr[4];
#pragma unroll
            for (int ii = 0; ii < 4; ii++) pr[ii] = sP[(r0 + ii) * PS + j];
            const float4 v0 = *(const float4*)&sV[j * VS + tj * 8];
            const float4 v1 = *(const float4*)&sV[j * VS + tj * 8 + 4];
#pragma unroll
            for (int ii = 0; ii < 4; ii++) {
                acc[ii][0] = fmaf(pr[ii], v0.x, acc[ii][0]);
                acc[ii][1] = fmaf(pr[ii], v0.y, acc[ii][1]);
                acc[ii][2] = fmaf(pr[ii], v0.z, acc[ii][2]);
                acc[ii][3] = fmaf(pr[ii], v0.w, acc[ii][3]);
                acc[ii][4] = fmaf(pr[ii], v1.x, acc[ii][4]);
                acc[ii][5] = fmaf(pr[ii], v1.y, acc[ii][5]);
                acc[ii][6] = fmaf(pr[ii], v1.z, acc[ii][6]);
                acc[ii][7] = fmaf(pr[ii], v1.w, acc[ii][7]);
            }
        }
    }

#pragma unroll
    for (int ii = 0; ii < 4; ii++) {
        const float inv = 1.f / l[ii];
        const size_t o = (bT + q0 + r0 + ii) * (size_t)(H_ * VD) + h * VD + tj * 8;
#pragma unroll
        for (int c = 0; c < 8; c++) {
            __nv_bfloat16 hh, ll;
            split2(acc[ii][c] * inv, hh, ll);
            Oh[o + c] = hh;
            Ol[o + c] = ll;
        }
    }
}

// ---------------- host glue ----------------
template <typename Tp>
static Tp* sym_addr(const void* symbol) {
    void* p = nullptr;
    cudaGetSymbolAddress(&p, symbol);
    return (Tp*)p;
}

extern "C" void kernel_launch(void* const* d_in, const int* in_sizes, int n_in,
                              void* d_out, int out_size)
{
    const float* hidden    = (const float*)d_in[0];
    const int*   positions = (const int*)  d_in[1];
    const float* w_qa  = (const float*)d_in[2];
    const float* g_qa  = (const float*)d_in[3];
    const float* w_qb  = (const float*)d_in[4];
    const float* w_kva = (const float*)d_in[5];
    const float* g_kva = (const float*)d_in[6];
    const float* w_kvb = (const float*)d_in[7];
    const float* w_o   = (const float*)d_in[8];

    float* out      = (float*)d_out;
    float* out_ckv  = out + (size_t)MT * D_;
    float* out_kr   = out_ckv + (size_t)MT * KVR;

    float* p_qlora = sym_addr<float>(g_qlora);
    float* p_q     = sym_addr<float>(g_q);
    float* p_kvc   = sym_addr<float>(g_kvc);
    float* p_kv    = sym_addr<float>(g_kv);
    float* p_krope = sym_addr<float>(g_krope);

    __nv_bfloat16* p_hid_h = sym_addr<__nv_bfloat16>(hid_h);
    __nv_bfloat16* p_hid_l = sym_addr<__nv_bfloat16>(hid_l);
    __nv_bfloat16* p_qlo_h = sym_addr<__nv_bfloat16>(qlo_h);
    __nv_bfloat16* p_qlo_l = sym_addr<__nv_bfloat16>(qlo_l);
    __nv_bfloat16* p_ckv_h = sym_addr<__nv_bfloat16>(ckv_h);
    __nv_bfloat16* p_ckv_l = sym_addr<__nv_bfloat16>(ckv_l);
    __nv_bfloat16* p_atn_h = sym_addr<__nv_bfloat16>(atn_h);
    __nv_bfloat16* p_atn_l = sym_addr<__nv_bfloat16>(atn_l);
    __nv_bfloat16* p_wqaT_h = sym_addr<__nv_bfloat16>(wqaT_h);
    __nv_bfloat16* p_wqaT_l = sym_addr<__nv_bfloat16>(wqaT_l);
    __nv_bfloat16* p_wqbT_h = sym_addr<__nv_bfloat16>(wqbT_h);
    __nv_bfloat16* p_wqbT_l = sym_addr<__nv_bfloat16>(wqbT_l);
    __nv_bfloat16* p_wkvaT_h = sym_addr<__nv_bfloat16>(wkvaT_h);
    __nv_bfloat16* p_wkvaT_l = sym_addr<__nv_bfloat16>(wkvaT_l);
    __nv_bfloat16* p_wkvbT_h = sym_addr<__nv_bfloat16>(wkvbT_h);
    __nv_bfloat16* p_wkvbT_l = sym_addr<__nv_bfloat16>(wkvbT_l);
    __nv_bfloat16* p_woT_h = sym_addr<__nv_bfloat16>(woT_h);
    __nv_bfloat16* p_woT_l = sym_addr<__nv_bfloat16>(woT_l);

    static bool attr_set = false;
    if (!attr_set) {
        cudaFuncSetAttribute(attn_kernel, cudaFuncAttributeMaxDynamicSharedMemorySize, ATTN_SMEM);
        cudaFuncSetAttribute(mmagemm_kernel, cudaFuncAttributeMaxDynamicSharedMemorySize, GSMEM);
        attr_set = true;
    }

    // --- operand prep ---
    split_kernel<<<(unsigned)(((size_t)MT * D_ + 255) / 256), 256>>>(hidden, p_hid_h, p_hid_l, (size_t)MT * D_);
    transpose_split_kernel<<<dim3(QL / 32, D_ / 32), 256>>>(w_qa, p_wqaT_h, p_wqaT_l, D_, QL);
    transpose_split_kernel<<<dim3(QN / 32, QL / 32), 256>>>(w_qb, p_wqbT_h, p_wqbT_l, QL, QN);
    transpose_split_kernel<<<dim3(KVCP / 32, D_ / 32), 256>>>(w_kva, p_wkvaT_h, p_wkvaT_l, D_, KVC);
    transpose_split_kernel<<<dim3(KVN / 32, KVR / 32), 256>>>(w_kvb, p_wkvbT_h, p_wkvbT_l, KVR, KVN);
    transpose_split_kernel<<<dim3(D_ / 32, D_ / 32), 256>>>(w_o, p_woT_h, p_woT_l, D_, D_);

    // --- pipeline ---
    mmagemm_kernel<<<dim3(QL / 128, MT / 128), 256, GSMEM>>>(
        p_hid_h, p_hid_l, p_wqaT_h, p_wqaT_l, p_qlora, MT, QL, D_);
    rms_split_kernel<<<MT, 256>>>(p_qlora, g_qa, QL, p_qlo_h, p_qlo_l);
    mmagemm_kernel<<<dim3(QN / 128, MT / 128), 256, GSMEM>>>(
        p_qlo_h, p_qlo_l, p_wqbT_h, p_wqbT_l, p_q, MT, QN, QL);
    mmagemm_kernel<<<dim3(KVCP / 128, MT / 128), 256, GSMEM>>>(
        p_hid_h, p_hid_l, p_wkvaT_h, p_wkvaT_l, p_kvc, MT, KVC, D_);
    rmskv_rope_kernel<<<MT, 256>>>(p_kvc, g_kva, out_ckv, p_ckv_h, p_ckv_l, out_kr, p_krope);
    mmagemm_kernel<<<dim3(KVN / 128, MT / 128), 256, GSMEM>>>(
        p_ckv_h, p_ckv_l, p_wkvbT_h, p_wkvbT_l, p_kv, MT, KVN, KVR);
    rope_q_kernel<<<MT, 1024>>>(p_q, positions);
    attn_kernel<<<dim3(T_ / 64, H_, B_), 256, ATTN_SMEM>>>(p_q, p_kv, p_krope, p_atn_h, p_atn_l);
    mmagemm_kernel<<<dim3(D_ / 128, MT / 128), 256, GSMEM>>>(
        p_atn_h, p_atn_l, p_woT_h, p_woT_l, out, MT, D_, D_);
}

// round 5
// speedup vs baseline: 9.2100x; 1.7582x over previous
#include <cuda_runtime.h>
#include <cuda_bf16.h>
#include <math.h>
#include <stdint.h>

// ---------------- problem constants ----------------
constexpr int B_   = 2;
constexpr int T_   = 2048;
constexpr int D_   = 2048;
constexpr int H_   = 16;
constexpr int NOPE = 128;
constexpr int ROPE = 64;
constexpr int QH   = NOPE + ROPE;          // 192
constexpr int QL   = H_ * QH / 4;          // 768
constexpr int KVR  = 512;
constexpr int VD   = 128;
constexpr int MT   = B_ * T_;              // 4096 rows
constexpr int KVN  = H_ * (NOPE + VD);     // 4096
constexpr int QN   = H_ * QH;              // 3072
constexpr int KVC  = KVR + ROPE;           // 576
constexpr int KVCP = 640;                  // padded to 128
constexpr float EPS = 1e-6f;
constexpr float SCALE = 0.07216878364870322f; // 192^-0.5

// ---------------- static scratch ----------------
__device__ float g_qlora[(size_t)MT * QL];
__device__ float g_q[(size_t)MT * QN];
__device__ float g_kvc[(size_t)MT * KVC];
__device__ float g_kv[(size_t)MT * KVN];
__device__ float g_krope[(size_t)MT * ROPE];

__device__ __nv_bfloat16 hid_h[(size_t)MT * D_],  hid_l[(size_t)MT * D_];
__device__ __nv_bfloat16 qlo_h[(size_t)MT * QL],  qlo_l[(size_t)MT * QL];
__device__ __nv_bfloat16 ckv_h[(size_t)MT * KVR], ckv_l[(size_t)MT * KVR];
__device__ __nv_bfloat16 atn_h[(size_t)MT * D_],  atn_l[(size_t)MT * D_];

// attention operands (per-head layouts)
__device__ __nv_bfloat16 aq_h[(size_t)B_ * H_ * T_ * QH], aq_l[(size_t)B_ * H_ * T_ * QH];
__device__ __nv_bfloat16 ak_h[(size_t)B_ * H_ * T_ * QH], ak_l[(size_t)B_ * H_ * T_ * QH];
__device__ __nv_bfloat16 avt_h[(size_t)B_ * H_ * VD * T_], avt_l[(size_t)B_ * H_ * VD * T_];

__device__ __nv_bfloat16 wqaT_h[(size_t)QL * D_],    wqaT_l[(size_t)QL * D_];
__device__ __nv_bfloat16 wqbT_h[(size_t)QN * QL],    wqbT_l[(size_t)QN * QL];
__device__ __nv_bfloat16 wkvaT_h[(size_t)KVCP * D_], wkvaT_l[(size_t)KVCP * D_];
__device__ __nv_bfloat16 wkvbT_h[(size_t)KVN * KVR], wkvbT_l[(size_t)KVN * KVR];
__device__ __nv_bfloat16 woT_h[(size_t)D_ * D_],     woT_l[(size_t)D_ * D_];

// ---------------- PTX helpers (sm_80-class only) ----------------
__device__ __forceinline__ uint32_t smem_u32(const void* p) {
    uint32_t a;
    asm("{ .reg .u64 t; cvta.to.shared.u64 t, %1; cvt.u32.u64 %0, t; }"
        : "=r"(a) : "l"(p));
    return a;
}
__device__ __forceinline__ void split2(float x, __nv_bfloat16& h, __nv_bfloat16& l) {
    h = __float2bfloat16(x);
    l = __float2bfloat16(x - __bfloat162float(h));
}
__device__ __forceinline__ void cp16(uint32_t dst, const void* src) {
    asm volatile("cp.async.cg.shared.global [%0], [%1], 16;"
                 :: "r"(dst), "l"(src) : "memory");
}
__device__ __forceinline__ void ldm4(uint32_t* r, uint32_t a) {
    asm volatile("ldmatrix.sync.aligned.m8n8.x4.shared.b16 {%0,%1,%2,%3}, [%4];"
                 : "=r"(r[0]), "=r"(r[1]), "=r"(r[2]), "=r"(r[3]) : "r"(a));
}
__device__ __forceinline__ void ldm2(uint32_t* r, uint32_t a) {
    asm volatile("ldmatrix.sync.aligned.m8n8.x2.shared.b16 {%0,%1}, [%2];"
                 : "=r"(r[0]), "=r"(r[1]) : "r"(a));
}
__device__ __forceinline__ void mma16816(float* d, const uint32_t* a, const uint32_t* b) {
    asm volatile(
        "mma.sync.aligned.m16n8k16.row.col.f32.bf16.bf16.f32 "
        "{%0,%1,%2,%3}, {%4,%5,%6,%7}, {%8,%9}, {%0,%1,%2,%3};"
        : "+f"(d[0]), "+f"(d[1]), "+f"(d[2]), "+f"(d[3])
        : "r"(a[0]), "r"(a[1]), "r"(a[2]), "r"(a[3]), "r"(b[0]), "r"(b[1]));
}
__device__ __forceinline__ void pack2(float a, float b, uint32_t& hi, uint32_t& lo) {
    __nv_bfloat16 ah = __float2bfloat16(a), bh = __float2bfloat16(b);
    __nv_bfloat16 al = __float2bfloat16(a - __bfloat162float(ah));
    __nv_bfloat16 bl = __float2bfloat16(b - __bfloat162float(bh));
    __nv_bfloat162 vh; vh.x = ah; vh.y = bh;
    __nv_bfloat162 vl; vl.x = al; vl.y = bl;
    hi = *reinterpret_cast<uint32_t*>(&vh);
    lo = *reinterpret_cast<uint32_t*>(&vl);
}

// ---------------- split-bf16 HMMA GEMM (unchanged from R4) ----------------
constexpr int GSMEM = 65536;

__global__ __launch_bounds__(256) void mmagemm_kernel(
    const __nv_bfloat16* __restrict__ Ah, const __nv_bfloat16* __restrict__ Al,
    const __nv_bfloat16* __restrict__ Bh, const __nv_bfloat16* __restrict__ Bl,
    float* __restrict__ C, int M, int N, int K)
{
    extern __shared__ char smraw[];
    const uint32_t sbase0 = smem_u32(smraw);

    const int tid = threadIdx.x, lane = tid & 31, wid = tid >> 5;
    const int wm = wid >> 2, wn = wid & 3;
    const int m0 = blockIdx.y * 128, n0 = blockIdx.x * 128;
    const int KT = K >> 5;

    float acc[4][4][4];
#pragma unroll
    for (int i = 0; i < 4; i++)
#pragma unroll
        for (int j = 0; j < 4; j++)
#pragma unroll
            for (int q = 0; q < 4; q++) acc[i][j][q] = 0.f;

    const int lrow0 = tid >> 2, lc0 = tid & 3;
    const int lrow1 = (tid + 256) >> 2, lc1 = (tid + 256) & 3;

    auto load_stage = [&](int buf, int kc) {
        const uint32_t sb = sbase0 + buf * 32768;
        {
            const uint32_t cp_ = (uint32_t)(lc0 ^ ((lrow0 & 7) >> 1));
            const uint32_t off = (uint32_t)lrow0 * 64u + cp_ * 16u;
            const size_t ga = (size_t)(m0 + lrow0) * K + kc + lc0 * 8;
            const size_t gb = (size_t)(n0 + lrow0) * K + kc + lc0 * 8;
            cp16(sb + off,          Ah + ga);
            cp16(sb + 8192 + off,   Al + ga);
            cp16(sb + 16384 + off,  Bh + gb);
            cp16(sb + 24576 + off,  Bl + gb);
        }
        {
            const uint32_t cp_ = (uint32_t)(lc1 ^ ((lrow1 & 7) >> 1));
            const uint32_t off = (uint32_t)lrow1 * 64u + cp_ * 16u;
            const size_t ga = (size_t)(m0 + lrow1) * K + kc + lc1 * 8;
            const size_t gb = (size_t)(n0 + lrow1) * K + kc + lc1 * 8;
            cp16(sb + off,          Ah + ga);
            cp16(sb + 8192 + off,   Al + ga);
            cp16(sb + 16384 + off,  Bh + gb);
            cp16(sb + 24576 + off,  Bl + gb);
        }
        asm volatile("cp.async.commit_group;" ::: "memory");
    };

    load_stage(0, 0);

    for (int kt = 0; kt < KT; kt++) {
        const int buf = kt & 1;
        if (kt + 1 < KT) {
            load_stage(buf ^ 1, (kt + 1) * 32);
            asm volatile("cp.async.wait_group 1;" ::: "memory");
        } else {
            asm volatile("cp.async.wait_group 0;" ::: "memory");
        }
        __syncthreads();

        const uint32_t aAh = sbase0 + buf * 32768;
        const uint32_t aAl = aAh + 8192;
        const uint32_t aBh = aAh + 16384;
        const uint32_t aBl = aAh + 24576;

#pragma unroll
        for (int ks = 0; ks < 2; ks++) {
            uint32_t fAh[4][4], fAl[4][4], fBh[4][2], fBl[4][2];
#pragma unroll
            for (int mf = 0; mf < 4; mf++) {
                const int row = wm * 64 + mf * 16 + (lane & 15);
                const int c = ks * 2 + (lane >> 4);
                const uint32_t off = (uint32_t)row * 64u
                                   + (uint32_t)((c ^ ((row & 7) >> 1)) * 16);
                ldm4(fAh[mf], aAh + off);
                ldm4(fAl[mf], aAl + off);
            }
#pragma unroll
            for (int nf = 0; nf < 4; nf++) {
                const int row = wn * 32 + nf * 8 + (lane & 7);
                const int c = ks * 2 + ((lane >> 3) & 1);
                const uint32_t off = (uint32_t)row * 64u
                                   + (uint32_t)((c ^ ((row & 7) >> 1)) * 16);
                ldm2(fBh[nf], aBh + off);
                ldm2(fBl[nf], aBl + off);
            }
#pragma unroll
            for (int mf = 0; mf < 4; mf++)
#pragma unroll
                for (int nf = 0; nf < 4; nf++)
                    mma16816(acc[mf][nf], fAh[mf], fBh[nf]);
#pragma unroll
            for (int mf = 0; mf < 4; mf++)
#pragma unroll
                for (int nf = 0; nf < 4; nf++)
                    mma16816(acc[mf][nf], fAl[mf], fBh[nf]);
#pragma unroll
            for (int mf = 0; mf < 4; mf++)
#pragma unroll
                for (int nf = 0; nf < 4; nf++)
                    mma16816(acc[mf][nf], fAh[mf], fBl[nf]);
        }
        __syncthreads();
    }

    const int g = lane >> 2, tq = lane & 3;
#pragma unroll
    for (int mf = 0; mf < 4; mf++) {
        const int row = m0 + wm * 64 + mf * 16 + g;
#pragma unroll
        for (int nf = 0; nf < 4; nf++) {
            const int col = n0 + wn * 32 + nf * 8 + tq * 2;
            if (col < N) {
                float2 v0 = make_float2(acc[mf][nf][0], acc[mf][nf][1]);
                float2 v1 = make_float2(acc[mf][nf][2], acc[mf][nf][3]);
                *(float2*)(C + (size_t)row * N + col) = v0;
                *(float2*)(C + (size_t)(row + 8) * N + col) = v1;
            }
        }
    }
}

// ---------------- weight transpose + split ----------------
__global__ __launch_bounds__(256) void transpose_split_kernel(
    const float* __restrict__ W, __nv_bfloat16* __restrict__ Th,
    __nv_bfloat16* __restrict__ Tl, int K, int N)
{
    __shared__ float t[32][33];
    const int tx = threadIdx.x & 31, ty = threadIdx.x >> 5;
    const int n0 = blockIdx.x * 32, k0 = blockIdx.y * 32;
#pragma unroll
    for (int i = 0; i < 4; i++) {
        const int k = k0 + ty + i * 8, n = n0 + tx;
        t[ty + i * 8][tx] = (n < N) ? W[(size_t)k * N + n] : 0.f;
    }
    __syncthreads();
#pragma unroll
    for (int i = 0; i < 4; i++) {
        const int n = n0 + ty + i * 8, k = k0 + tx;
        __nv_bfloat16 h, l;
        split2(t[tx][ty + i * 8], h, l);
        Th[(size_t)n * K + k] = h;
        Tl[(size_t)n * K + k] = l;
    }
}

__global__ __launch_bounds__(256) void split_kernel(
    const float* __restrict__ X, __nv_bfloat16* __restrict__ H,
    __nv_bfloat16* __restrict__ L, size_t n)
{
    const size_t i = (size_t)blockIdx.x * blockDim.x + threadIdx.x;
    if (i < n) {
        __nv_bfloat16 h, l;
        split2(X[i], h, l);
        H[i] = h; L[i] = l;
    }
}

// ---------------- block reduce ----------------
__device__ __forceinline__ float block_sum(float v) {
    __shared__ float red[8];
    __shared__ float tot;
    const int lane = threadIdx.x & 31, w = threadIdx.x >> 5;
#pragma unroll
    for (int o = 16; o; o >>= 1) v += __shfl_xor_sync(0xffffffffu, v, o);
    if (lane == 0) red[w] = v;
    __syncthreads();
    if (w == 0) {
        float x = (threadIdx.x < (blockDim.x >> 5)) ? red[threadIdx.x] : 0.f;
#pragma unroll
        for (int o = 4; o; o >>= 1) x += __shfl_xor_sync(0xffffffffu, x, o);
        if (threadIdx.x == 0) tot = x;
    }
    __syncthreads();
    return tot;
}

// ---------------- RMSNorm -> hi/lo ----------------
__global__ __launch_bounds__(256) void rms_split_kernel(
    const float* __restrict__ X, const float* __restrict__ g, int ncols,
    __nv_bfloat16* __restrict__ Oh, __nv_bfloat16* __restrict__ Ol)
{
    const int row = blockIdx.x;
    const float* x = X + (size_t)row * ncols;
    float ss = 0.f;
    for (int c = threadIdx.x; c < ncols; c += blockDim.x) { float v = x[c]; ss += v * v; }
    const float total = block_sum(ss);
    const float rs = rsqrtf(total / (float)ncols + EPS);
    for (int c = threadIdx.x; c < ncols; c += blockDim.x) {
        __nv_bfloat16 h, l;
        split2(x[c] * rs * g[c], h, l);
        Oh[(size_t)row * ncols + c] = h;
        Ol[(size_t)row * ncols + c] = l;
    }
}

// ---------------- kv path: rms(c_kv) + rope(k) ----------------
__global__ __launch_bounds__(256) void rmskv_rope_kernel(
    const float* __restrict__ kvc, const float* __restrict__ g_kva_,
    float* __restrict__ out_ckv, __nv_bfloat16* __restrict__ ch,
    __nv_bfloat16* __restrict__ cl, float* __restrict__ out_kr,
    float* __restrict__ kr_rot)
{
    const int row = blockIdx.x;
    const int t = row % T_;
    const float* x = kvc + (size_t)row * KVC;
    float ss = 0.f;
    for (int c = threadIdx.x; c < KVR; c += blockDim.x) { float v = x[c]; ss += v * v; }
    const float total = block_sum(ss);
    const float rs = rsqrtf(total / (float)KVR + EPS);
    for (int c = threadIdx.x; c < KVR; c += blockDim.x) {
        const float v = x[c] * rs * g_kva_[c];
        out_ckv[(size_t)row * KVR + c] = v;
        __nv_bfloat16 h, l;
        split2(v, h, l);
        ch[(size_t)row * KVR + c] = h;
        cl[(size_t)row * KVR + c] = l;
    }
    if (threadIdx.x < ROPE) {
        const int d = threadIdx.x;
        const float raw = x[KVR + d];
        out_kr[(size_t)row * ROPE + d] = raw;
        const int j = d & 31;
        const float inv = powf(10000.f, -(float)(2 * j) / (float)ROPE);
        const float fr = (float)t * inv;
        const float other = (d < 32) ? -x[KVR + d + 32] : x[KVR + d - 32];
        kr_rot[(size_t)row * ROPE + d] = raw * cosf(fr) + other * sinf(fr);
    }
}

// ---------------- q rope + split to [B,H,T,192] (pre-scaled by SCALE) ----------------
__global__ __launch_bounds__(192) void rope_q_split_kernel(
    const float* __restrict__ q, const int* __restrict__ positions,
    __nv_bfloat16* __restrict__ Qh, __nv_bfloat16* __restrict__ Qlo)
{
    const int row = blockIdx.x;           // b*T + t
    const int h = blockIdx.y;
    const int d = threadIdx.x;            // 0..191
    const int b = row / T_, t = row % T_;
    const int pos = positions[row];
    const float* qr = q + (size_t)row * QN + h * QH;
    float v = qr[d];
    if (d >= NOPE) {
        const int dr = d - NOPE;
        const int j = dr & 31;
        const float inv = powf(10000.f, -(float)(2 * j) / (float)ROPE);
        const float fr = (float)pos * inv;
        const float other = (dr < 32) ? -qr[d + 32] : qr[d - 32];
        v = v * cosf(fr) + other * sinf(fr);
    }
    v *= SCALE;
    __nv_bfloat16 hh, ll;
    split2(v, hh, ll);
    const size_t o = (((size_t)b * H_ + h) * T_ + t) * QH + d;
    Qh[o] = hh; Qlo[o] = ll;
}

// ---------------- k (nope + roped-rope dup) split to [B,H,T,192] ----------------
__global__ __launch_bounds__(256) void prep_k_kernel(
    const float* __restrict__ kv, const float* __restrict__ kr,
    __nv_bfloat16* __restrict__ Kh, __nv_bfloat16* __restrict__ Kl)
{
    const int row = blockIdx.x;           // b*T + t
    const int b = row / T_, t = row % T_;
    for (int idx = threadIdx.x; idx < H_ * QH; idx += 256) {
        const int h = idx / QH, d = idx % QH;
        const float v = (d < NOPE) ? kv[(size_t)row * KVN + h * (NOPE + VD) + d]
                                   : kr[(size_t)row * ROPE + (d - NOPE)];
        __nv_bfloat16 hh, ll;
        split2(v, hh, ll);
        const size_t o = (((size_t)b * H_ + h) * T_ + t) * QH + d;
        Kh[o] = hh; Kl[o] = ll;
    }
}

// ---------------- v transpose + split to [B,H,128,T] ----------------
__global__ __launch_bounds__(256) void prep_vt_kernel(
    const float* __restrict__ kv,
    __nv_bfloat16* __restrict__ Vh, __nv_bfloat16* __restrict__ Vl)
{
    __shared__ float s[128 * 66];         // [d][t] with pad
    const int bh = blockIdx.x;            // b*H + h
    const int t0 = blockIdx.y * 64;
    const int b = bh / H_, h = bh % H_;
    for (int idx = threadIdx.x; idx < 64 * 32; idx += 256) {
        const int t = idx >> 5, c4 = idx & 31;
        const size_t row = (size_t)b * T_ + t0 + t;
        const float4 v = *(const float4*)(kv + row * KVN + h * (NOPE + VD) + NOPE + c4 * 4);
        s[(c4 * 4 + 0) * 66 + t] = v.x;
        s[(c4 * 4 + 1) * 66 + t] = v.y;
        s[(c4 * 4 + 2) * 66 + t] = v.z;
        s[(c4 * 4 + 3) * 66 + t] = v.w;
    }
    __syncthreads();
    for (int idx = threadIdx.x; idx < 128 * 8; idx += 256) {
        const int d = idx >> 3, tg = idx & 7;
        __nv_bfloat16 hv[8], lv[8];
#pragma unroll
        for (int k = 0; k < 8; k++)
            split2(s[d * 66 + tg * 8 + k], hv[k], lv[k]);
        const size_t o = (((size_t)bh) * VD + d) * T_ + t0 + tg * 8;
        *(uint4*)(Vh + o) = *(uint4*)hv;
        *(uint4*)(Vl + o) = *(uint4*)lv;
    }
}

// ---------------- HMMA flash attention ----------------
// BM=128 queries, BN=64 keys/chunk, 8 warps (warp w: rows 16w..16w+15).
// smem: Ql persistent 48KB @0; K buffers (Kh24K+Kl24K)x2 @49152; Vt (16K+16K)x2 @147456.
constexpr int AT_SMEM = 212992;

__global__ __launch_bounds__(256) void attn_mma_kernel(
    const __nv_bfloat16* __restrict__ Qh, const __nv_bfloat16* __restrict__ Qlo,
    const __nv_bfloat16* __restrict__ Kh, const __nv_bfloat16* __restrict__ Kl,
    const __nv_bfloat16* __restrict__ Vth, const __nv_bfloat16* __restrict__ Vtl,
    __nv_bfloat16* __restrict__ Oh, __nv_bfloat16* __restrict__ Ol)
{
    extern __shared__ char smraw[];
    const uint32_t sb = smem_u32(smraw);
    const int tid = threadIdx.x, lane = tid & 31, w = tid >> 5;
    const int qt = blockIdx.x, h = blockIdx.y, b = blockIdx.z;
    const int q0 = qt * 128;
    const size_t bhT = ((size_t)b * H_ + h) * T_;
    const size_t bhV = ((size_t)b * H_ + h) * VD;

    // --- stage Q: Ql -> @0 (persistent), Qh -> @49152 (transient) ---
#pragma unroll
    for (int i = 0; i < 12; i++) {
        const int g = tid + i * 256;
        const int row = g / 24, cg = g % 24;
        const uint32_t dst = (uint32_t)(row * 384 + ((cg ^ (row & 7)) * 16));
        const __nv_bfloat16* src = Qh + (bhT + q0 + row) * QH + cg * 8;
        const __nv_bfloat16* srl = Qlo + (bhT + q0 + row) * QH + cg * 8;
        cp16(sb + 49152 + dst, src);
        cp16(sb + dst, srl);
    }
    asm volatile("cp.async.commit_group;" ::: "memory");
    asm volatile("cp.async.wait_group 0;" ::: "memory");
    __syncthreads();

    // extract Qh fragments into registers
    uint32_t fQh[12][4];
    {
        const int row = w * 16 + (lane & 15);
#pragma unroll
        for (int kf = 0; kf < 12; kf++) {
            const int cg = kf * 2 + (lane >> 4);
            const uint32_t off = (uint32_t)(row * 384 + ((cg ^ (row & 7)) * 16));
            ldm4(fQh[kf], sb + 49152 + off);
        }
    }
    __syncthreads();   // Qh staging area free -> becomes K buffer 0

    const int nch = 2 * qt + 2;

    auto load_kv = [&](int buf, int ch) {
        const int s0 = ch * 64;
        const uint32_t kb = sb + 49152 + buf * 49152;
        const uint32_t vb = sb + 147456 + buf * 32768;
#pragma unroll
        for (int i = 0; i < 6; i++) {
            const int g = tid + i * 256;
            const int row = g / 24, cg = g % 24;
            const uint32_t dst = kb + (uint32_t)(row * 384 + ((cg ^ (row & 7)) * 16));
            cp16(dst,          Kh + (bhT + s0 + row) * QH + cg * 8);
            cp16(dst + 24576,  Kl + (bhT + s0 + row) * QH + cg * 8);
        }
#pragma unroll
        for (int i = 0; i < 4; i++) {
            const int g = tid + i * 256;
            const int d = g >> 3, sg = g & 7;
            const uint32_t dst = vb + (uint32_t)(d * 128 + ((sg ^ (d & 7)) * 16));
            cp16(dst,          Vth + (bhV + d) * T_ + s0 + sg * 8);
            cp16(dst + 16384,  Vtl + (bhV + d) * T_ + s0 + sg * 8);
        }
        asm volatile("cp.async.commit_group;" ::: "memory");
    };

    load_kv(0, 0);
    load_kv(1, 1);

    const int gr_a = q0 + w * 16 + (lane >> 2);
    const int gr_b = gr_a + 8;
    float m_a = -1e30f, m_b = -1e30f, l_a = 0.f, l_b = 0.f;
    float oacc[16][4];
#pragma unroll
    for (int i = 0; i < 16; i++)
#pragma unroll
        for (int q = 0; q < 4; q++) oacc[i][q] = 0.f;

    for (int ch = 0; ch < nch; ch++) {
        const int buf = ch & 1;
        const int s0 = ch * 64;
        if (ch + 1 < nch) asm volatile("cp.async.wait_group 1;" ::: "memory");
        else              asm volatile("cp.async.wait_group 0;" ::: "memory");
        __syncthreads();

        const uint32_t kb = sb + 49152 + buf * 49152;
        const uint32_t vb = sb + 147456 + buf * 32768;

        // ---- scores = Q K^T (3-term split) ----
        float sc[8][4];
#pragma unroll
        for (int nf = 0; nf < 8; nf++)
#pragma unroll
            for (int q = 0; q < 4; q++) sc[nf][q] = 0.f;

#pragma unroll
        for (int kf = 0; kf < 12; kf++) {
            // Ql A-frag from smem
            uint32_t fql[4];
            {
                const int row = w * 16 + (lane & 15);
                const int cg = kf * 2 + (lane >> 4);
                ldm4(fql, sb + (uint32_t)(row * 384 + ((cg ^ (row & 7)) * 16)));
            }
#pragma unroll
            for (int np = 0; np < 4; np++) {
                const int row = np * 16 + (lane & 15);
                const int cg = kf * 2 + (lane >> 4);
                const uint32_t off = (uint32_t)(row * 384 + ((cg ^ (row & 7)) * 16));
                uint32_t rh[4], rl[4];
                ldm4(rh, kb + off);
                ldm4(rl, kb + 24576 + off);
                uint32_t b0h[2] = { rh[0], rh[2] }, b1h[2] = { rh[1], rh[3] };
                uint32_t b0l[2] = { rl[0], rl[2] }, b1l[2] = { rl[1], rl[3] };
                mma16816(sc[2 * np],     fQh[kf], b0h);
                mma16816(sc[2 * np],     fql,     b0h);
                mma16816(sc[2 * np],     fQh[kf], b0l);
                mma16816(sc[2 * np + 1], fQh[kf], b1h);
                mma16816(sc[2 * np + 1], fql,     b1h);
                mma16816(sc[2 * np + 1], fQh[kf], b1l);
            }
        }

        // ---- mask + online softmax (rows within 4-lane groups) ----
        float mxa = -1e30f, mxb = -1e30f;
#pragma unroll
        for (int nf = 0; nf < 8; nf++) {
            const int cb = s0 + nf * 8 + (lane & 3) * 2;
            if (cb     > gr_a) sc[nf][0] = -1e30f;
            if (cb + 1 > gr_a) sc[nf][1] = -1e30f;
            if (cb     > gr_b) sc[nf][2] = -1e30f;
            if (cb + 1 > gr_b) sc[nf][3] = -1e30f;
            mxa = fmaxf(mxa, fmaxf(sc[nf][0], sc[nf][1]));
            mxb = fmaxf(mxb, fmaxf(sc[nf][2], sc[nf][3]));
        }
        mxa = fmaxf(mxa, __shfl_xor_sync(0xffffffffu, mxa, 1));
        mxa = fmaxf(mxa, __shfl_xor_sync(0xffffffffu, mxa, 2));
        mxb = fmaxf(mxb, __shfl_xor_sync(0xffffffffu, mxb, 1));
        mxb = fmaxf(mxb, __shfl_xor_sync(0xffffffffu, mxb, 2));
        const float nma = fmaxf(m_a, mxa), nmb = fmaxf(m_b, mxb);
        const float alpha_a = __expf(m_a - nma), alpha_b = __expf(m_b - nmb);
        m_a = nma; m_b = nmb;

        float suma = 0.f, sumb = 0.f;
        uint32_t Ph[4][4], Pl[4][4];
#pragma unroll
        for (int kf2 = 0; kf2 < 4; kf2++) {
#pragma unroll
            for (int half = 0; half < 2; half++) {
                const int nf = 2 * kf2 + half;
                const float p0 = __expf(sc[nf][0] - nma);
                const float p1 = __expf(sc[nf][1] - nma);
                const float p2 = __expf(sc[nf][2] - nmb);
                const float p3 = __expf(sc[nf][3] - nmb);
                suma += p0 + p1; sumb += p2 + p3;
                pack2(p0, p1, Ph[kf2][half * 2],     Pl[kf2][half * 2]);
                pack2(p2, p3, Ph[kf2][half * 2 + 1], Pl[kf2][half * 2 + 1]);
            }
        }
        suma += __shfl_xor_sync(0xffffffffu, suma, 1);
        suma += __shfl_xor_sync(0xffffffffu, suma, 2);
        sumb += __shfl_xor_sync(0xffffffffu, sumb, 1);
        sumb += __shfl_xor_sync(0xffffffffu, sumb, 2);
        l_a = l_a * alpha_a + suma;
        l_b = l_b * alpha_b + sumb;
#pragma unroll
        for (int nf = 0; nf < 16; nf++) {
            oacc[nf][0] *= alpha_a; oacc[nf][1] *= alpha_a;
            oacc[nf][2] *= alpha_b; oacc[nf][3] *= alpha_b;
        }

        // ---- O += P V (3-term split), B = Vt [128d x 64s] ----
#pragma unroll
        for (int kf2 = 0; kf2 < 4; kf2++) {
#pragma unroll
            for (int np = 0; np < 8; np++) {
                const int row = np * 16 + (lane & 15);
                const int cg = kf2 * 2 + (lane >> 4);
                const uint32_t off = (uint32_t)(row * 128 + ((cg ^ (row & 7)) * 16));
                uint32_t rh[4], rl[4];
                ldm4(rh, vb + off);
                ldm4(rl, vb + 16384 + off);
                uint32_t b0h[2] = { rh[0], rh[2] }, b1h[2] = { rh[1], rh[3] };
                uint32_t b0l[2] = { rl[0], rl[2] }, b1l[2] = { rl[1], rl[3] };
                mma16816(oacc[2 * np],     Ph[kf2], b0h);
                mma16816(oacc[2 * np],     Pl[kf2], b0h);
                mma16816(oacc[2 * np],     Ph[kf2], b0l);
                mma16816(oacc[2 * np + 1], Ph[kf2], b1h);
                mma16816(oacc[2 * np + 1], Pl[kf2], b1h);
                mma16816(oacc[2 * np + 1], Ph[kf2], b1l);
            }
        }

        __syncthreads();   // all warps done with buf before it is reloaded
        if (ch + 2 < nch) load_kv(buf, ch + 2);
    }

    // ---- epilogue: normalize + split-write for w_o GEMM ----
    const float inva = 1.f / l_a, invb = 1.f / l_b;
#pragma unroll
    for (int nf = 0; nf < 16; nf++) {
        const int d = h * VD + nf * 8 + (lane & 3) * 2;
        uint32_t hia, loa, hib, lob;
        pack2(oacc[nf][0] * inva, oacc[nf][1] * inva, hia, loa);
        pack2(oacc[nf][2] * invb, oacc[nf][3] * invb, hib, lob);
        const size_t oa = ((size_t)b * T_ + gr_a) * (size_t)D_ + d;
        const size_t ob = ((size_t)b * T_ + gr_b) * (size_t)D_ + d;
        *(uint32_t*)(Oh + oa) = hia; *(uint32_t*)(Ol + oa) = loa;
        *(uint32_t*)(Oh + ob) = hib; *(uint32_t*)(Ol + ob) = lob;
    }
}

// ---------------- host glue ----------------
template <typename Tp>
static Tp* sym_addr(const void* symbol) {
    void* p = nullptr;
    cudaGetSymbolAddress(&p, symbol);
    return (Tp*)p;
}

extern "C" void kernel_launch(void* const* d_in, const int* in_sizes, int n_in,
                              void* d_out, int out_size)
{
    const float* hidden    = (const float*)d_in[0];
    const int*   positions = (const int*)  d_in[1];
    const float* w_qa  = (const float*)d_in[2];
    const float* g_qa  = (const float*)d_in[3];
    const float* w_qb  = (const float*)d_in[4];
    const float* w_kva = (const float*)d_in[5];
    const float* g_kva = (const float*)d_in[6];
    const float* w_kvb = (const float*)d_in[7];
    const float* w_o   = (const float*)d_in[8];

    float* out      = (float*)d_out;
    float* out_ckv  = out + (size_t)MT * D_;
    float* out_kr   = out_ckv + (size_t)MT * KVR;

    float* p_qlora = sym_addr<float>(g_qlora);
    float* p_q     = sym_addr<float>(g_q);
    float* p_kvc   = sym_addr<float>(g_kvc);
    float* p_kv    = sym_addr<float>(g_kv);
    float* p_krope = sym_addr<float>(g_krope);

    __nv_bfloat16* p_hid_h = sym_addr<__nv_bfloat16>(hid_h);
    __nv_bfloat16* p_hid_l = sym_addr<__nv_bfloat16>(hid_l);
    __nv_bfloat16* p_qlo_h = sym_addr<__nv_bfloat16>(qlo_h);
    __nv_bfloat16* p_qlo_l = sym_addr<__nv_bfloat16>(qlo_l);
    __nv_bfloat16* p_ckv_h = sym_addr<__nv_bfloat16>(ckv_h);
    __nv_bfloat16* p_ckv_l = sym_addr<__nv_bfloat16>(ckv_l);
    __nv_bfloat16* p_atn_h = sym_addr<__nv_bfloat16>(atn_h);
    __nv_bfloat16* p_atn_l = sym_addr<__nv_bfloat16>(atn_l);
    __nv_bfloat16* p_aq_h = sym_addr<__nv_bfloat16>(aq_h);
    __nv_bfloat16* p_aq_l = sym_addr<__nv_bfloat16>(aq_l);
    __nv_bfloat16* p_ak_h = sym_addr<__nv_bfloat16>(ak_h);
    __nv_bfloat16* p_ak_l = sym_addr<__nv_bfloat16>(ak_l);
    __nv_bfloat16* p_avt_h = sym_addr<__nv_bfloat16>(avt_h);
    __nv_bfloat16* p_avt_l = sym_addr<__nv_bfloat16>(avt_l);
    __nv_bfloat16* p_wqaT_h = sym_addr<__nv_bfloat16>(wqaT_h);
    __nv_bfloat16* p_wqaT_l = sym_addr<__nv_bfloat16>(wqaT_l);
    __nv_bfloat16* p_wqbT_h = sym_addr<__nv_bfloat16>(wqbT_h);
    __nv_bfloat16* p_wqbT_l = sym_addr<__nv_bfloat16>(wqbT_l);
    __nv_bfloat16* p_wkvaT_h = sym_addr<__nv_bfloat16>(wkvaT_h);
    __nv_bfloat16* p_wkvaT_l = sym_addr<__nv_bfloat16>(wkvaT_l);
    __nv_bfloat16* p_wkvbT_h = sym_addr<__nv_bfloat16>(wkvbT_h);
    __nv_bfloat16* p_wkvbT_l = sym_addr<__nv_bfloat16>(wkvbT_l);
    __nv_bfloat16* p_woT_h = sym_addr<__nv_bfloat16>(woT_h);
    __nv_bfloat16* p_woT_l = sym_addr<__nv_bfloat16>(woT_l);

    static bool attr_set = false;
    if (!attr_set) {
        cudaFuncSetAttribute(mmagemm_kernel, cudaFuncAttributeMaxDynamicSharedMemorySize, GSMEM);
        cudaFuncSetAttribute(attn_mma_kernel, cudaFuncAttributeMaxDynamicSharedMemorySize, AT_SMEM);
        attr_set = true;
    }

    // --- operand prep ---
    split_kernel<<<(unsigned)(((size_t)MT * D_ + 255) / 256), 256>>>(hidden, p_hid_h, p_hid_l, (size_t)MT * D_);
    transpose_split_kernel<<<dim3(QL / 32, D_ / 32), 256>>>(w_qa, p_wqaT_h, p_wqaT_l, D_, QL);
    transpose_split_kernel<<<dim3(QN / 32, QL / 32), 256>>>(w_qb, p_wqbT_h, p_wqbT_l, QL, QN);
    transpose_split_kernel<<<dim3(KVCP / 32, D_ / 32), 256>>>(w_kva, p_wkvaT_h, p_wkvaT_l, D_, KVC);
    transpose_split_kernel<<<dim3(KVN / 32, KVR / 32), 256>>>(w_kvb, p_wkvbT_h, p_wkvbT_l, KVR, KVN);
    transpose_split_kernel<<<dim3(D_ / 32, D_ / 32), 256>>>(w_o, p_woT_h, p_woT_l, D_, D_);

    // --- pipeline ---
    mmagemm_kernel<<<dim3(QL / 128, MT / 128), 256, GSMEM>>>(
        p_hid_h, p_hid_l, p_wqaT_h, p_wqaT_l, p_qlora, MT, QL, D_);
    rms_split_kernel<<<MT, 256>>>(p_qlora, g_qa, QL, p_qlo_h, p_qlo_l);
    mmagemm_kernel<<<dim3(QN / 128, MT / 128), 256, GSMEM>>>(
        p_qlo_h, p_qlo_l, p_wqbT_h, p_wqbT_l, p_q, MT, QN, QL);
    mmagemm_kernel<<<dim3(KVCP / 128, MT / 128), 256, GSMEM>>>(
        p_hid_h, p_hid_l, p_wkvaT_h, p_wkvaT_l, p_kvc, MT, KVC, D_);
    rmskv_rope_kernel<<<MT, 256>>>(p_kvc, g_kva, out_ckv, p_ckv_h, p_ckv_l, out_kr, p_krope);
    mmagemm_kernel<<<dim3(KVN / 128, MT / 128), 256, GSMEM>>>(
        p_ckv_h, p_ckv_l, p_wkvbT_h, p_wkvbT_l, p_kv, MT, KVN, KVR);

    rope_q_split_kernel<<<dim3(MT, H_), 192>>>(p_q, positions, p_aq_h, p_aq_l);
    prep_k_kernel<<<MT, 256>>>(p_kv, p_krope, p_ak_h, p_ak_l);
    prep_vt_kernel<<<dim3(B_ * H_, T_ / 64), 256>>>(p_kv, p_avt_h, p_avt_l);

    attn_mma_kernel<<<dim3(T_ / 128, H_, B_), 256, AT_SMEM>>>(
        p_aq_h, p_aq_l, p_ak_h, p_ak_l, p_avt_h, p_avt_l, p_atn_h, p_atn_l);

    mmagemm_kernel<<<dim3(D_ / 128, MT / 128), 256, GSMEM>>>(
        p_atn_h, p_atn_l, p_woT_h, p_woT_l, out, MT, D_, D_);
}